// round 11
// baseline (speedup 1.0000x reference)
#include <cuda_runtime.h>
#include <cuda_fp16.h>
#include <cstddef>
#include <cstdint>

#define N_AQI 35
#define N_MEO 18
#define NTOT  53
#define F_OUT 64
#define CTXD  60
#define BATCH 4096
#define NEGV  (-1e12f)
#define LALPHA 0.2f

#define WT_STRIDE  20
#define FULL_STRIDE 28
#define PRE_BLOCKS 32

// K-column permutation: col c -> node j. MEO first (even-aligned pairs everywhere).
//   c in [0,18)  -> j = 35 + c   (MEO)
//   c in [18,53) -> j = c - 18   (AQI)

// ---------------- batch-independent precomputed state ----------------
__device__ __align__(16) float g_biasP[NTOT * 56];
__device__ __align__(16) unsigned long long g_maskP[NTOT];
__device__ __align__(16) float g_wsrc[2][2][FULL_STRIDE];
__device__ __align__(16) float g_wdst[2][2][FULL_STRIDE];
__device__ __align__(16) float g_WxaT[64 * WT_STRIDE];
__device__ __align__(16) float g_WxmT[64 * WT_STRIDE];

__global__ void precompute_kernel(
    const float* __restrict__ ctx,
    const float* __restrict__ adj_norm,
    const float* __restrict__ a_aa, const float* __restrict__ a_am,
    const float* __restrict__ a_ma, const float* __restrict__ a_mm,
    const float* __restrict__ W_ua, const float* __restrict__ W_um,
    const float* __restrict__ W_xa, const float* __restrict__ W_xm,
    const int*   __restrict__ adj)
{
    __shared__ float s_cs[NTOT][2];
    __shared__ float s_ct[NTOT][2];
    const int tid = threadIdx.x;
    const int gid = blockIdx.x * 256 + tid;
    const int gstr = PRE_BLOCKS * 256;
    const float* A[2][2] = {{a_aa, a_am}, {a_ma, a_mm}};

    for (int id = tid; id < NTOT * 4; id += 256) {
        int i = id % NTOT;
        int sel = id / NTOT;
        if (sel < 2) {
            int rb = (i < N_AQI) ? 0 : 1;
            const float* a = A[rb][sel];
            float acc = 0.f;
            for (int c = 0; c < CTXD; c++) acc += ctx[i * CTXD + c] * a[64 + c];
            s_cs[i][sel] = acc;
        } else {
            int rb = sel - 2;
            int cb = (i < N_AQI) ? 0 : 1;
            const float* a = A[rb][cb];
            float acc = 0.f;
            for (int c = 0; c < CTXD; c++) acc += ctx[i * CTXD + c] * a[188 + c];
            s_ct[i][rb] = acc;
        }
    }

    for (int id = gid; id < 2 * 2 * 2 * FULL_STRIDE; id += gstr) {
        int k = id % FULL_STRIDE;
        int r = id / FULL_STRIDE;
        int which = r >> 2;
        int t0 = (r >> 1) & 1;
        int t1 = r & 1;
        const float* W = (t0 == 0) ? W_ua : W_um;
        int K = (t0 == 0) ? 24 : 26;
        float acc = 0.f;
        if (k < K) {
            const float* a = (which == 0) ? A[t0][t1] : A[t1][t0];
            int off = (which == 0) ? 0 : 124;
            for (int f = 0; f < 64; f++) acc += W[k * 64 + f] * a[off + f];
        }
        if (which == 0) g_wsrc[t0][t1][k] = acc;
        else            g_wdst[t0][t1][k] = acc;
    }

    for (int id = gid; id < 64 * WT_STRIDE; id += gstr) {
        int f = id / WT_STRIDE, k = id % WT_STRIDE;
        g_WxaT[id] = (k < 16) ? W_xa[k * 64 + f] : 0.f;
        g_WxmT[id] = (k < 16) ? W_xm[k * 64 + f] : 0.f;
    }

    for (int i = gid; i < NTOT; i += gstr) {
        unsigned long long m = 0ull;
        for (int c = 0; c < NTOT; c++) {
            int j = (c < 18) ? 35 + c : c - 18;
            if (adj[i * NTOT + j] > 0) m |= (1ull << c);
        }
        g_maskP[i] = m;
    }
    __syncthreads();

    for (int id = gid; id < NTOT * 56; id += gstr) {
        int i = id / 56, c = id % 56;
        float v = 0.f;
        if (c < NTOT) {
            int j = (c < 18) ? 35 + c : c - 18;
            int rb = (i < N_AQI) ? 0 : 1;
            int cb = (j < N_AQI) ? 0 : 1;
            v = s_cs[i][cb] + s_ct[j][rb] + adj_norm[i * NTOT + j] * A[rb][cb][248];
        }
        g_biasP[id] = v;
    }
}

// ---------------- helpers ----------------
__device__ __forceinline__ unsigned long long fma2(unsigned long long a,
                                                   unsigned long long b,
                                                   unsigned long long c)
{
    unsigned long long d;
    asm("fma.rn.f32x2 %0, %1, %2, %3;" : "=l"(d) : "l"(a), "l"(b), "l"(c));
    return d;
}
__device__ __forceinline__ float lo32(unsigned long long v) { return __uint_as_float((unsigned)v); }
__device__ __forceinline__ float hi32(unsigned long long v) { return __uint_as_float((unsigned)(v >> 32)); }

__device__ __forceinline__ uint32_t smem_u32(const void* p) {
    uint32_t a;
    asm("{ .reg .u64 t; cvta.to.shared.u64 t, %1; cvt.u32.u64 %0, t; }" : "=r"(a) : "l"(p));
    return a;
}
__device__ __forceinline__ uint32_t pack2h(float a, float b) {
    __half2 v = __floats2half2_rn(a, b);    // a -> low halfword
    return *reinterpret_cast<uint32_t*>(&v);
}
__device__ __forceinline__ void ldmx4(uint32_t addr, uint32_t& r0, uint32_t& r1,
                                      uint32_t& r2, uint32_t& r3)
{
    asm volatile("ldmatrix.sync.aligned.m8n8.x4.shared.b16 {%0,%1,%2,%3}, [%4];"
                 : "=r"(r0), "=r"(r1), "=r"(r2), "=r"(r3) : "r"(addr));
}
__device__ __forceinline__ void mma16816(float* d, const uint32_t* a, uint32_t b0, uint32_t b1)
{
    asm volatile(
        "mma.sync.aligned.m16n8k16.row.col.f32.f16.f16.f32 "
        "{%0,%1,%2,%3}, {%4,%5,%6,%7}, {%8,%9}, {%0,%1,%2,%3};"
        : "+f"(d[0]), "+f"(d[1]), "+f"(d[2]), "+f"(d[3])
        : "r"(a[0]), "r"(a[1]), "r"(a[2]), "r"(a[3]), "r"(b0), "r"(b1));
}

// A tile aliased with the gather buffer: s_full dead after phase 2; A written in phase 3.
union SmemAU {
    unsigned char A[64 * 128];
    float full[56 * FULL_STRIDE];
};

// ---------------- main kernel: TWO batch elements per CTA ----------------
__global__ __launch_bounds__(256, 5) void hgat_kernel(
    const float* __restrict__ aqi_inp, const float* __restrict__ meo_inp,
    const float* __restrict__ aqi_idE, const float* __restrict__ aqi_monthE,
    const float* __restrict__ aqi_weekdayE, const float* __restrict__ aqi_hourE,
    const float* __restrict__ meo_windE, const float* __restrict__ meo_idE,
    const float* __restrict__ meo_monthE, const float* __restrict__ meo_weekdayE,
    const float* __restrict__ meo_hourE,
    const int* __restrict__ aqi_ex, const int* __restrict__ meo_ex,
    float* __restrict__ out)
{
    __shared__ __align__(1024) SmemAU s_U[2];                 // A tiles / gather buffers
    __shared__ __align__(1024) unsigned char s_B[2][64 * 128];
    __shared__ __align__(16) float s_S[2][108];
    __shared__ __align__(16) float s_T[2][108];               // permuted-col; col 53 zeroed

    const int tid = threadIdx.x;
    const int wid = tid >> 5;
    const int lane = tid & 31;
    const int b0 = blockIdx.x * 2;

    // ---- Phase 0: B K-pad zeroing, feature copy, embedding gather (both batches) ----
    {
        const float4 z4 = make_float4(0.f, 0.f, 0.f, 0.f);
        // zero logical bytes [96,128) of every row of the 2 B tiles
        if (tid < 128) {
            int row = tid & 63;
            unsigned char* base = s_B[tid >> 6];
            uint32_t sw = (uint32_t)((row & 7) << 4);
            *reinterpret_cast<float4*>(base + row * 128 + (96u ^ sw)) = z4;
            *reinterpret_cast<float4*>(base + row * 128 + (112u ^ sw)) = z4;
        }
        // input features: 2 x 53 rows x 4 float4
        for (int id = tid; id < 2 * NTOT * 4; id += 256) {
            int e = id >= NTOT * 4;
            int id2 = id - e * NTOT * 4;
            int row = id2 >> 2, q = id2 & 3;
            int bb = b0 + e;
            float4 v = (row < N_AQI)
                ? *reinterpret_cast<const float4*>(&aqi_inp[((size_t)bb * N_AQI + row) * 16 + 4 * q])
                : *reinterpret_cast<const float4*>(&meo_inp[((size_t)bb * N_MEO + (row - N_AQI)) * 16 + 4 * q]);
            *reinterpret_cast<float4*>(&s_U[e].full[row * FULL_STRIDE + 4 * q]) = v;
        }
        // AQI embeddings: 2 x 35 rows x 4 slots
        for (int id = tid; id < 2 * N_AQI * 4; id += 256) {
            int e = id >= N_AQI * 4;
            int id2 = id - e * N_AQI * 4;
            int row = id2 >> 2, ee = id2 & 3;
            int ix = aqi_ex[((size_t)(b0 + e) * N_AQI + row) * 4 + ee];
            const float* tab = (ee == 0) ? aqi_idE : (ee == 1) ? aqi_monthE
                             : (ee == 2) ? aqi_weekdayE : aqi_hourE;
            *reinterpret_cast<float2*>(&s_U[e].full[row * FULL_STRIDE + 16 + 2 * ee]) =
                *reinterpret_cast<const float2*>(&tab[ix * 2]);
        }
        // MEO embeddings: 2 x 18 rows x 5 slots
        for (int id = tid; id < 2 * N_MEO * 5; id += 256) {
            int e = id >= N_MEO * 5;
            int id2 = id - e * N_MEO * 5;
            int row = id2 / 5, ee = id2 - row * 5;
            int ix = meo_ex[((size_t)(b0 + e) * N_MEO + row) * 5 + ee];
            const float* tab = (ee == 0) ? meo_windE : (ee == 1) ? meo_idE
                             : (ee == 2) ? meo_monthE : (ee == 3) ? meo_weekdayE : meo_hourE;
            *reinterpret_cast<float2*>(&s_U[e].full[(N_AQI + row) * FULL_STRIDE + 16 + 2 * ee]) =
                *reinterpret_cast<const float2*>(&tab[ix * 2]);
        }
        // s_full pads: AQI cols 24-27, MEO cols 26-27; s_T col 53
        if (tid < 2 * N_AQI) {
            int e = tid >= N_AQI, i = tid - e * N_AQI;
            *reinterpret_cast<float4*>(&s_U[e].full[i * FULL_STRIDE + 24]) = z4;
        } else if (tid < 2 * N_AQI + 2 * N_MEO) {
            int k = tid - 2 * N_AQI;
            int e = k >= N_MEO, i = N_AQI + k - e * N_MEO;
            s_U[e].full[i * FULL_STRIDE + 26] = 0.f;
            s_U[e].full[i * FULL_STRIDE + 27] = 0.f;
        } else if (tid < 2 * N_AQI + 2 * N_MEO + 4) {
            int k = tid - (2 * N_AQI + 2 * N_MEO);
            s_T[k >> 1][106 + (k & 1)] = 0.f;
        }
    }
    __syncthreads();

    // ---- Phase 1: projxT -> fp16 pairs into B tile (both batches) ----
    // thread: e = tid>>7, f = (tid>>1)&63, rg = tid&1
    {
        const int e = tid >> 7;
        const int f = (tid >> 1) & 63, rg = tid & 1;
        const uint32_t sw = (uint32_t)((f & 7) << 4);
        unsigned char* rowB = s_B[e] + f * 128;
        const float* full = s_U[e].full;

        // MEO pass: pair p = rg + 2r, p < 9; c0 = 2p, nodes 35+c0, 36+c0
        {
            const float* wt = g_WxmT + f * WT_STRIDE;
            unsigned long long acc[5][2];
            #pragma unroll
            for (int r = 0; r < 5; r++) { acc[r][0] = 0ull; acc[r][1] = 0ull; }
            #pragma unroll
            for (int kg = 0; kg < 4; kg++) {
                ulonglong2 wv = *reinterpret_cast<const ulonglong2*>(wt + 4 * kg);
                #pragma unroll
                for (int r = 0; r < 5; r++) {
                    int p = rg + 2 * r;
                    if (p < 9) {
                        const float* x0 = &full[(N_AQI + 2 * p) * FULL_STRIDE + 4 * kg];
                        ulonglong2 a0 = *reinterpret_cast<const ulonglong2*>(x0);
                        ulonglong2 a1 = *reinterpret_cast<const ulonglong2*>(x0 + FULL_STRIDE);
                        acc[r][0] = fma2(wv.x, a0.x, acc[r][0]);
                        acc[r][0] = fma2(wv.y, a0.y, acc[r][0]);
                        acc[r][1] = fma2(wv.x, a1.x, acc[r][1]);
                        acc[r][1] = fma2(wv.y, a1.y, acc[r][1]);
                    }
                }
            }
            #pragma unroll
            for (int r = 0; r < 5; r++) {
                int p = rg + 2 * r;
                if (p < 9) {
                    float p0 = lo32(acc[r][0]) + hi32(acc[r][0]);
                    float p1 = lo32(acc[r][1]) + hi32(acc[r][1]);
                    uint32_t off = ((uint32_t)(4 * p)) ^ sw;
                    *reinterpret_cast<uint32_t*>(rowB + off) = pack2h(p0, p1);
                }
            }
        }
        // AQI pass: pair p = 9 + rg + 2r, p < 27; c0 = 2p, nodes c0-18, c0-17
        {
            const float* wt = g_WxaT + f * WT_STRIDE;
            unsigned long long acc[9][2];
            #pragma unroll
            for (int r = 0; r < 9; r++) { acc[r][0] = 0ull; acc[r][1] = 0ull; }
            #pragma unroll
            for (int kg = 0; kg < 4; kg++) {
                ulonglong2 wv = *reinterpret_cast<const ulonglong2*>(wt + 4 * kg);
                #pragma unroll
                for (int r = 0; r < 9; r++) {
                    int p = 9 + rg + 2 * r;
                    if (p < 27) {
                        const float* x0 = &full[(2 * p - 18) * FULL_STRIDE + 4 * kg];
                        ulonglong2 a0 = *reinterpret_cast<const ulonglong2*>(x0);
                        ulonglong2 a1 = *reinterpret_cast<const ulonglong2*>(x0 + FULL_STRIDE);
                        acc[r][0] = fma2(wv.x, a0.x, acc[r][0]);
                        acc[r][0] = fma2(wv.y, a0.y, acc[r][0]);
                        acc[r][1] = fma2(wv.x, a1.x, acc[r][1]);
                        acc[r][1] = fma2(wv.y, a1.y, acc[r][1]);
                    }
                }
            }
            #pragma unroll
            for (int r = 0; r < 9; r++) {
                int p = 9 + rg + 2 * r;
                if (p < 27) {
                    float p0 = lo32(acc[r][0]) + hi32(acc[r][0]);
                    float p1 = (p == 26) ? 0.f : lo32(acc[r][1]) + hi32(acc[r][1]);
                    uint32_t off = ((uint32_t)(4 * p)) ^ sw;
                    *reinterpret_cast<uint32_t*>(rowB + off) = pack2h(p0, p1);
                }
            }
        }
    }

    // ---- Phase 2: S[i][cb]; T -> permuted-col layout (both batches) ----
    for (int id = tid; id < 2 * NTOT * 4; id += 256) {
        int e = id >= NTOT * 4;
        int id2 = id - e * NTOT * 4;
        int i = id2 % NTOT;
        int sel = id2 / NTOT;
        int rt = (i < N_AQI) ? 0 : 1;
        const float4* xr = reinterpret_cast<const float4*>(&s_U[e].full[i * FULL_STRIDE]);
        const float4* wv = reinterpret_cast<const float4*>(
            (sel < 2) ? g_wsrc[rt][sel] : g_wdst[rt][sel - 2]);
        float acc = 0.f;
        #pragma unroll
        for (int m = 0; m < 7; m++) {
            float4 x = xr[m], w = wv[m];
            acc += x.x * w.x + x.y * w.y + x.z * w.z + x.w * w.w;
        }
        if (sel < 2) s_S[e][i * 2 + sel] = acc;
        else {
            int c = (i < N_AQI) ? i + 18 : i - N_AQI;
            s_T[e][c * 2 + (sel - 2)] = acc;
        }
    }
    __syncthreads();
    // s_full is DEAD from here; its bytes become the A tiles.

    // ---- Phase 3: masked softmax -> packed fp16x2 into A tile (both batches) ----
    // warps 0-3: batch 0 rows {w,w+4,...}; warps 4-7: batch 1.
    // Lanes 27/28 zero this row's K-pad bytes [108,128) (disjoint from data bytes).
    {
        const int e = wid >> 2, w4 = wid & 3;
        const bool act = (lane < 27);
        const int c0 = 2 * lane, c1 = c0 + 1;
        float4 tv = act ? *reinterpret_cast<const float4*>(&s_T[e][c0 * 2])
                        : make_float4(0.f, 0.f, 0.f, 0.f);
        const bool meo0 = (c0 < 18), meo1 = (c1 < 18);
        const uint32_t colOff = (uint32_t)(4 * lane);
        unsigned char* tileA = s_U[e].A;

        for (int i = w4; i < NTOT; i += 4) {
            const int rb = (i < N_AQI) ? 0 : 1;
            const uint32_t swrow = (uint32_t)((i & 7) << 4);
            // K-pad zeroing for this row (cols 54-63)
            if (lane == 27)
                *reinterpret_cast<uint32_t*>(tileA + i * 128 + (108u ^ swrow)) = 0u;
            if (lane == 28)
                *reinterpret_cast<float4*>(tileA + i * 128 + (112u ^ swrow)) =
                    make_float4(0.f, 0.f, 0.f, 0.f);

            float e0 = -3.4e38f, e1 = -3.4e38f;
            if (act) {
                unsigned long long M = g_maskP[i];
                float2 sv = *reinterpret_cast<const float2*>(&s_S[e][i * 2]);
                float2 bp = *reinterpret_cast<const float2*>(&g_biasP[i * 56 + c0]);
                float s0 = meo0 ? sv.y : sv.x;
                float s1 = meo1 ? sv.y : sv.x;
                float t0 = rb ? tv.y : tv.x;
                float t1 = rb ? tv.w : tv.z;
                float v0 = s0 + t0 + bp.x; v0 = (v0 >= 0.f) ? v0 : LALPHA * v0;
                float v1 = s1 + t1 + bp.y; v1 = (v1 >= 0.f) ? v1 : LALPHA * v1;
                e0 = ((M >> c0) & 1ull) ? v0 : NEGV;
                e1 = ((M >> c1) & 1ull) ? v1 : NEGV;
                if (c1 >= NTOT) e1 = -3.4e38f;
            }
            float mx = fmaxf(e0, e1);
            #pragma unroll
            for (int o = 16; o > 0; o >>= 1) mx = fmaxf(mx, __shfl_xor_sync(0xffffffffu, mx, o));
            float p0 = act ? __expf(e0 - mx) : 0.f;
            float p1 = (act && c1 < NTOT) ? __expf(e1 - mx) : 0.f;
            float sum = p0 + p1;
            #pragma unroll
            for (int o = 16; o > 0; o >>= 1) sum += __shfl_xor_sync(0xffffffffu, sum, o);
            float inv = 1.f / sum;
            if (act) {
                uint32_t off = (uint32_t)(i * 128) + (colOff ^ swrow);
                *reinterpret_cast<uint32_t*>(tileA + off) = pack2h(p0 * inv, p1 * inv);
            }
        }
    }
    __syncthreads();

    // ---- Phase 4: D = A @ B^T via mma.sync m16n8k16 fp16 ----
    // warp: e = wid>>2; within batch: mg = (wid>>1)&1 (32 rows), ng = wid&1 (32 cols).
    {
        const int e = wid >> 2;
        const int mg = (wid >> 1) & 1, ng = wid & 1;
        const int lm = lane >> 3, lr = lane & 7;
        const uint32_t aBase = smem_u32(s_U[e].A);
        const uint32_t bBase = smem_u32(s_B[e]);
        const uint32_t swx = (uint32_t)(lr << 4);
        const uint32_t aCol = (uint32_t)((lm >> 1) << 4);
        const uint32_t bCol = (uint32_t)((lm & 1) << 4);
        const int bb = b0 + e;

        uint32_t aRB[2], bRB[2];
        #pragma unroll
        for (int mt = 0; mt < 2; mt++) {
            int row = mg * 32 + mt * 16 + (lm & 1) * 8 + lr;
            aRB[mt] = aBase + (uint32_t)(row * 128);
        }
        #pragma unroll
        for (int ntp = 0; ntp < 2; ntp++) {
            int row = ng * 32 + ntp * 16 + (lm >> 1) * 8 + lr;
            bRB[ntp] = bBase + (uint32_t)(row * 128);
        }

        float d[2][4][4];
        #pragma unroll
        for (int mt = 0; mt < 2; mt++)
            #pragma unroll
            for (int nt = 0; nt < 4; nt++)
                #pragma unroll
                for (int q = 0; q < 4; q++) d[mt][nt][q] = 0.f;

        #pragma unroll
        for (int k = 0; k < 4; k++) {
            uint32_t a[2][4];
            #pragma unroll
            for (int mt = 0; mt < 2; mt++)
                ldmx4(aRB[mt] + (((uint32_t)(k << 5) + aCol) ^ swx),
                      a[mt][0], a[mt][1], a[mt][2], a[mt][3]);
            #pragma unroll
            for (int ntp = 0; ntp < 2; ntp++) {
                uint32_t b0r, b1r, b2r, b3r;
                ldmx4(bRB[ntp] + (((uint32_t)(k << 5) + bCol) ^ swx), b0r, b1r, b2r, b3r);
                #pragma unroll
                for (int mt = 0; mt < 2; mt++) {
                    mma16816(d[mt][ntp * 2 + 0], a[mt], b0r, b1r);
                    mma16816(d[mt][ntp * 2 + 1], a[mt], b2r, b3r);
                }
            }
        }

        // Epilogue: direct float2 stores.
        const int r0l = lane >> 2;
        const int cl = (lane & 3) * 2;
        #pragma unroll
        for (int mt = 0; mt < 2; mt++) {
            #pragma unroll
            for (int nt = 0; nt < 4; nt++) {
                int r0 = mg * 32 + mt * 16 + r0l;
                int r1 = r0 + 8;
                int col = ng * 32 + nt * 8 + cl;
                if (r0 < NTOT) {
                    float* dst = (r0 < N_AQI)
                        ? out + ((size_t)bb * N_AQI + r0) * 64
                        : out + (size_t)BATCH * N_AQI * 64 + ((size_t)bb * N_MEO + (r0 - N_AQI)) * 64;
                    *reinterpret_cast<float2*>(dst + col) = make_float2(d[mt][nt][0], d[mt][nt][1]);
                }
                if (r1 < NTOT) {
                    float* dst = (r1 < N_AQI)
                        ? out + ((size_t)bb * N_AQI + r1) * 64
                        : out + (size_t)BATCH * N_AQI * 64 + ((size_t)bb * N_MEO + (r1 - N_AQI)) * 64;
                    *reinterpret_cast<float2*>(dst + col) = make_float2(d[mt][nt][2], d[mt][nt][3]);
                }
            }
        }
    }
}

extern "C" void kernel_launch(void* const* d_in, const int* in_sizes, int n_in,
                              void* d_out, int out_size)
{
    const float* aqi_inp      = (const float*)d_in[0];
    const float* meo_inp      = (const float*)d_in[1];
    const float* context_feat = (const float*)d_in[2];
    const float* adj_norm     = (const float*)d_in[3];
    const float* aqi_idE      = (const float*)d_in[4];
    const float* aqi_monthE   = (const float*)d_in[5];
    const float* aqi_weekdayE = (const float*)d_in[6];
    const float* aqi_hourE    = (const float*)d_in[7];
    const float* meo_windE    = (const float*)d_in[8];
    const float* meo_idE      = (const float*)d_in[9];
    const float* meo_monthE   = (const float*)d_in[10];
    const float* meo_weekdayE = (const float*)d_in[11];
    const float* meo_hourE    = (const float*)d_in[12];
    const float* W_xa         = (const float*)d_in[13];
    const float* W_xm         = (const float*)d_in[14];
    const float* W_ua         = (const float*)d_in[15];
    const float* W_um         = (const float*)d_in[16];
    const float* a_aa         = (const float*)d_in[17];
    const float* a_am         = (const float*)d_in[18];
    const float* a_ma         = (const float*)d_in[19];
    const float* a_mm         = (const float*)d_in[20];
    const int*   aqi_ex       = (const int*)d_in[21];
    const int*   meo_ex       = (const int*)d_in[22];
    const int*   adj          = (const int*)d_in[23];
    float* out = (float*)d_out;

    precompute_kernel<<<PRE_BLOCKS, 256>>>(context_feat, adj_norm,
                                           a_aa, a_am, a_ma, a_mm,
                                           W_ua, W_um, W_xa, W_xm, adj);
    hgat_kernel<<<BATCH / 2, 256>>>(aqi_inp, meo_inp,
                                    aqi_idE, aqi_monthE, aqi_weekdayE, aqi_hourE,
                                    meo_windE, meo_idE, meo_monthE, meo_weekdayE, meo_hourE,
                                    aqi_ex, meo_ex, out);
}

// round 12
// speedup vs baseline: 1.1259x; 1.1259x over previous
#include <cuda_runtime.h>
#include <cuda_fp16.h>
#include <cstddef>
#include <cstdint>

#define N_AQI 35
#define N_MEO 18
#define NTOT  53
#define F_OUT 64
#define CTXD  60
#define BATCH 4096
#define NEGV  (-1e12f)
#define LALPHA 0.2f

#define WT_STRIDE  20
#define FULL_STRIDE 28
#define PRE_BLOCKS 32

// K-column permutation: col c -> node j. MEO first (even-aligned pairs everywhere).
//   c in [0,18)  -> j = 35 + c   (MEO)
//   c in [18,53) -> j = c - 18   (AQI)

// ---------------- batch-independent precomputed state ----------------
__device__ __align__(16) float g_biasP[NTOT * 56];
__device__ __align__(16) unsigned long long g_maskP[NTOT];
__device__ __align__(16) float g_wsrc[2][2][FULL_STRIDE];
__device__ __align__(16) float g_wdst[2][2][FULL_STRIDE];
__device__ __align__(16) float g_WxaT[64 * WT_STRIDE];
__device__ __align__(16) float g_WxmT[64 * WT_STRIDE];

__global__ void precompute_kernel(
    const float* __restrict__ ctx,
    const float* __restrict__ adj_norm,
    const float* __restrict__ a_aa, const float* __restrict__ a_am,
    const float* __restrict__ a_ma, const float* __restrict__ a_mm,
    const float* __restrict__ W_ua, const float* __restrict__ W_um,
    const float* __restrict__ W_xa, const float* __restrict__ W_xm,
    const int*   __restrict__ adj)
{
    __shared__ float s_cs[NTOT][2];
    __shared__ float s_ct[NTOT][2];
    const int tid = threadIdx.x;
    const int gid = blockIdx.x * 256 + tid;
    const int gstr = PRE_BLOCKS * 256;
    const float* A[2][2] = {{a_aa, a_am}, {a_ma, a_mm}};

    for (int id = tid; id < NTOT * 4; id += 256) {
        int i = id % NTOT;
        int sel = id / NTOT;
        if (sel < 2) {
            int rb = (i < N_AQI) ? 0 : 1;
            const float* a = A[rb][sel];
            float acc = 0.f;
            for (int c = 0; c < CTXD; c++) acc += ctx[i * CTXD + c] * a[64 + c];
            s_cs[i][sel] = acc;
        } else {
            int rb = sel - 2;
            int cb = (i < N_AQI) ? 0 : 1;
            const float* a = A[rb][cb];
            float acc = 0.f;
            for (int c = 0; c < CTXD; c++) acc += ctx[i * CTXD + c] * a[188 + c];
            s_ct[i][rb] = acc;
        }
    }

    for (int id = gid; id < 2 * 2 * 2 * FULL_STRIDE; id += gstr) {
        int k = id % FULL_STRIDE;
        int r = id / FULL_STRIDE;
        int which = r >> 2;
        int t0 = (r >> 1) & 1;
        int t1 = r & 1;
        const float* W = (t0 == 0) ? W_ua : W_um;
        int K = (t0 == 0) ? 24 : 26;
        float acc = 0.f;
        if (k < K) {
            const float* a = (which == 0) ? A[t0][t1] : A[t1][t0];
            int off = (which == 0) ? 0 : 124;
            for (int f = 0; f < 64; f++) acc += W[k * 64 + f] * a[off + f];
        }
        if (which == 0) g_wsrc[t0][t1][k] = acc;
        else            g_wdst[t0][t1][k] = acc;
    }

    for (int id = gid; id < 64 * WT_STRIDE; id += gstr) {
        int f = id / WT_STRIDE, k = id % WT_STRIDE;
        g_WxaT[id] = (k < 16) ? W_xa[k * 64 + f] : 0.f;
        g_WxmT[id] = (k < 16) ? W_xm[k * 64 + f] : 0.f;
    }

    for (int i = gid; i < NTOT; i += gstr) {
        unsigned long long m = 0ull;
        for (int c = 0; c < NTOT; c++) {
            int j = (c < 18) ? 35 + c : c - 18;
            if (adj[i * NTOT + j] > 0) m |= (1ull << c);
        }
        g_maskP[i] = m;
    }
    __syncthreads();

    for (int id = gid; id < NTOT * 56; id += gstr) {
        int i = id / 56, c = id % 56;
        float v = 0.f;
        if (c < NTOT) {
            int j = (c < 18) ? 35 + c : c - 18;
            int rb = (i < N_AQI) ? 0 : 1;
            int cb = (j < N_AQI) ? 0 : 1;
            v = s_cs[i][cb] + s_ct[j][rb] + adj_norm[i * NTOT + j] * A[rb][cb][248];
        }
        g_biasP[id] = v;
    }
}

// ---------------- helpers ----------------
__device__ __forceinline__ unsigned long long fma2(unsigned long long a,
                                                   unsigned long long b,
                                                   unsigned long long c)
{
    unsigned long long d;
    asm("fma.rn.f32x2 %0, %1, %2, %3;" : "=l"(d) : "l"(a), "l"(b), "l"(c));
    return d;
}
__device__ __forceinline__ float lo32(unsigned long long v) { return __uint_as_float((unsigned)v); }
__device__ __forceinline__ float hi32(unsigned long long v) { return __uint_as_float((unsigned)(v >> 32)); }

__device__ __forceinline__ uint32_t smem_u32(const void* p) {
    uint32_t a;
    asm("{ .reg .u64 t; cvta.to.shared.u64 t, %1; cvt.u32.u64 %0, t; }" : "=r"(a) : "l"(p));
    return a;
}
__device__ __forceinline__ uint32_t pack2h(float a, float b) {
    __half2 v = __floats2half2_rn(a, b);    // a -> low halfword
    return *reinterpret_cast<uint32_t*>(&v);
}
__device__ __forceinline__ void ldmx4(uint32_t addr, uint32_t& r0, uint32_t& r1,
                                      uint32_t& r2, uint32_t& r3)
{
    asm volatile("ldmatrix.sync.aligned.m8n8.x4.shared.b16 {%0,%1,%2,%3}, [%4];"
                 : "=r"(r0), "=r"(r1), "=r"(r2), "=r"(r3) : "r"(addr));
}
__device__ __forceinline__ void mma16816(float* d, const uint32_t* a, uint32_t b0, uint32_t b1)
{
    asm volatile(
        "mma.sync.aligned.m16n8k16.row.col.f32.f16.f16.f32 "
        "{%0,%1,%2,%3}, {%4,%5,%6,%7}, {%8,%9}, {%0,%1,%2,%3};"
        : "+f"(d[0]), "+f"(d[1]), "+f"(d[2]), "+f"(d[3])
        : "r"(a[0]), "r"(a[1]), "r"(a[2]), "r"(a[3]), "r"(b0), "r"(b1));
}

// A tile aliased with the gather buffer: s_full dead after phase 2; A written in phase 3.
union SmemAU {
    unsigned char A[64 * 128];
    float full[56 * FULL_STRIDE];
};

// ---------------- main kernel: TWO batch elements per CTA ----------------
__global__ __launch_bounds__(256, 4) void hgat_kernel(
    const float* __restrict__ aqi_inp, const float* __restrict__ meo_inp,
    const float* __restrict__ aqi_idE, const float* __restrict__ aqi_monthE,
    const float* __restrict__ aqi_weekdayE, const float* __restrict__ aqi_hourE,
    const float* __restrict__ meo_windE, const float* __restrict__ meo_idE,
    const float* __restrict__ meo_monthE, const float* __restrict__ meo_weekdayE,
    const float* __restrict__ meo_hourE,
    const int* __restrict__ aqi_ex, const int* __restrict__ meo_ex,
    float* __restrict__ out)
{
    __shared__ __align__(1024) SmemAU s_U[2];                 // A tiles / gather buffers
    __shared__ __align__(1024) unsigned char s_B[2][64 * 128];
    __shared__ __align__(16) float s_S[2][108];
    __shared__ __align__(16) float s_T[2][108];               // permuted-col; col 53 zeroed

    const int tid = threadIdx.x;
    const int wid = tid >> 5;
    const int lane = tid & 31;
    const int b0 = blockIdx.x * 2;

    // ---- Phase 0: B K-pad zeroing, feature copy, embedding gather (both batches) ----
    {
        const float4 z4 = make_float4(0.f, 0.f, 0.f, 0.f);
        // zero logical bytes [96,128) of every row of the 2 B tiles
        if (tid < 128) {
            int row = tid & 63;
            unsigned char* base = s_B[tid >> 6];
            uint32_t sw = (uint32_t)((row & 7) << 4);
            *reinterpret_cast<float4*>(base + row * 128 + (96u ^ sw)) = z4;
            *reinterpret_cast<float4*>(base + row * 128 + (112u ^ sw)) = z4;
        }
        // input features: 2 x 53 rows x 4 float4
        for (int id = tid; id < 2 * NTOT * 4; id += 256) {
            int e = id >= NTOT * 4;
            int id2 = id - e * NTOT * 4;
            int row = id2 >> 2, q = id2 & 3;
            int bb = b0 + e;
            float4 v = (row < N_AQI)
                ? *reinterpret_cast<const float4*>(&aqi_inp[((size_t)bb * N_AQI + row) * 16 + 4 * q])
                : *reinterpret_cast<const float4*>(&meo_inp[((size_t)bb * N_MEO + (row - N_AQI)) * 16 + 4 * q]);
            *reinterpret_cast<float4*>(&s_U[e].full[row * FULL_STRIDE + 4 * q]) = v;
        }
        // AQI embeddings: 2 x 35 rows x 4 slots
        for (int id = tid; id < 2 * N_AQI * 4; id += 256) {
            int e = id >= N_AQI * 4;
            int id2 = id - e * N_AQI * 4;
            int row = id2 >> 2, ee = id2 & 3;
            int ix = aqi_ex[((size_t)(b0 + e) * N_AQI + row) * 4 + ee];
            const float* tab = (ee == 0) ? aqi_idE : (ee == 1) ? aqi_monthE
                             : (ee == 2) ? aqi_weekdayE : aqi_hourE;
            *reinterpret_cast<float2*>(&s_U[e].full[row * FULL_STRIDE + 16 + 2 * ee]) =
                *reinterpret_cast<const float2*>(&tab[ix * 2]);
        }
        // MEO embeddings: 2 x 18 rows x 5 slots
        for (int id = tid; id < 2 * N_MEO * 5; id += 256) {
            int e = id >= N_MEO * 5;
            int id2 = id - e * N_MEO * 5;
            int row = id2 / 5, ee = id2 - row * 5;
            int ix = meo_ex[((size_t)(b0 + e) * N_MEO + row) * 5 + ee];
            const float* tab = (ee == 0) ? meo_windE : (ee == 1) ? meo_idE
                             : (ee == 2) ? meo_monthE : (ee == 3) ? meo_weekdayE : meo_hourE;
            *reinterpret_cast<float2*>(&s_U[e].full[(N_AQI + row) * FULL_STRIDE + 16 + 2 * ee]) =
                *reinterpret_cast<const float2*>(&tab[ix * 2]);
        }
        // s_full pads: AQI cols 24-27, MEO cols 26-27; s_T col 53
        if (tid < 2 * N_AQI) {
            int e = tid >= N_AQI, i = tid - e * N_AQI;
            *reinterpret_cast<float4*>(&s_U[e].full[i * FULL_STRIDE + 24]) = z4;
        } else if (tid < 2 * N_AQI + 2 * N_MEO) {
            int k = tid - 2 * N_AQI;
            int e = k >= N_MEO, i = N_AQI + k - e * N_MEO;
            s_U[e].full[i * FULL_STRIDE + 26] = 0.f;
            s_U[e].full[i * FULL_STRIDE + 27] = 0.f;
        } else if (tid < 2 * N_AQI + 2 * N_MEO + 4) {
            int k = tid - (2 * N_AQI + 2 * N_MEO);
            s_T[k >> 1][106 + (k & 1)] = 0.f;
        }
    }
    __syncthreads();

    // ---- Phase 1: projxT -> fp16 pairs into B tile (both batches) ----
    // thread: e = tid>>7, f = (tid>>1)&63, rg = tid&1
    {
        const int e = tid >> 7;
        const int f = (tid >> 1) & 63, rg = tid & 1;
        const uint32_t sw = (uint32_t)((f & 7) << 4);
        unsigned char* rowB = s_B[e] + f * 128;
        const float* full = s_U[e].full;

        // MEO pass: pair p = rg + 2r, p < 9; c0 = 2p, nodes 35+c0, 36+c0
        {
            const float* wt = g_WxmT + f * WT_STRIDE;
            unsigned long long acc[5][2];
            #pragma unroll
            for (int r = 0; r < 5; r++) { acc[r][0] = 0ull; acc[r][1] = 0ull; }
            #pragma unroll
            for (int kg = 0; kg < 4; kg++) {
                ulonglong2 wv = *reinterpret_cast<const ulonglong2*>(wt + 4 * kg);
                #pragma unroll
                for (int r = 0; r < 5; r++) {
                    int p = rg + 2 * r;
                    if (p < 9) {
                        const float* x0 = &full[(N_AQI + 2 * p) * FULL_STRIDE + 4 * kg];
                        ulonglong2 a0 = *reinterpret_cast<const ulonglong2*>(x0);
                        ulonglong2 a1 = *reinterpret_cast<const ulonglong2*>(x0 + FULL_STRIDE);
                        acc[r][0] = fma2(wv.x, a0.x, acc[r][0]);
                        acc[r][0] = fma2(wv.y, a0.y, acc[r][0]);
                        acc[r][1] = fma2(wv.x, a1.x, acc[r][1]);
                        acc[r][1] = fma2(wv.y, a1.y, acc[r][1]);
                    }
                }
            }
            #pragma unroll
            for (int r = 0; r < 5; r++) {
                int p = rg + 2 * r;
                if (p < 9) {
                    float p0 = lo32(acc[r][0]) + hi32(acc[r][0]);
                    float p1 = lo32(acc[r][1]) + hi32(acc[r][1]);
                    uint32_t off = ((uint32_t)(4 * p)) ^ sw;
                    *reinterpret_cast<uint32_t*>(rowB + off) = pack2h(p0, p1);
                }
            }
        }
        // AQI pass: pair p = 9 + rg + 2r, p < 27; c0 = 2p, nodes c0-18, c0-17
        {
            const float* wt = g_WxaT + f * WT_STRIDE;
            unsigned long long acc[9][2];
            #pragma unroll
            for (int r = 0; r < 9; r++) { acc[r][0] = 0ull; acc[r][1] = 0ull; }
            #pragma unroll
            for (int kg = 0; kg < 4; kg++) {
                ulonglong2 wv = *reinterpret_cast<const ulonglong2*>(wt + 4 * kg);
                #pragma unroll
                for (int r = 0; r < 9; r++) {
                    int p = 9 + rg + 2 * r;
                    if (p < 27) {
                        const float* x0 = &full[(2 * p - 18) * FULL_STRIDE + 4 * kg];
                        ulonglong2 a0 = *reinterpret_cast<const ulonglong2*>(x0);
                        ulonglong2 a1 = *reinterpret_cast<const ulonglong2*>(x0 + FULL_STRIDE);
                        acc[r][0] = fma2(wv.x, a0.x, acc[r][0]);
                        acc[r][0] = fma2(wv.y, a0.y, acc[r][0]);
                        acc[r][1] = fma2(wv.x, a1.x, acc[r][1]);
                        acc[r][1] = fma2(wv.y, a1.y, acc[r][1]);
                    }
                }
            }
            #pragma unroll
            for (int r = 0; r < 9; r++) {
                int p = 9 + rg + 2 * r;
                if (p < 27) {
                    float p0 = lo32(acc[r][0]) + hi32(acc[r][0]);
                    float p1 = (p == 26) ? 0.f : lo32(acc[r][1]) + hi32(acc[r][1]);
                    uint32_t off = ((uint32_t)(4 * p)) ^ sw;
                    *reinterpret_cast<uint32_t*>(rowB + off) = pack2h(p0, p1);
                }
            }
        }
    }

    // ---- Phase 2: S[i][cb]; T -> permuted-col layout (both batches) ----
    for (int id = tid; id < 2 * NTOT * 4; id += 256) {
        int e = id >= NTOT * 4;
        int id2 = id - e * NTOT * 4;
        int i = id2 % NTOT;
        int sel = id2 / NTOT;
        int rt = (i < N_AQI) ? 0 : 1;
        const float4* xr = reinterpret_cast<const float4*>(&s_U[e].full[i * FULL_STRIDE]);
        const float4* wv = reinterpret_cast<const float4*>(
            (sel < 2) ? g_wsrc[rt][sel] : g_wdst[rt][sel - 2]);
        float acc = 0.f;
        #pragma unroll
        for (int m = 0; m < 7; m++) {
            float4 x = xr[m], w = wv[m];
            acc += x.x * w.x + x.y * w.y + x.z * w.z + x.w * w.w;
        }
        if (sel < 2) s_S[e][i * 2 + sel] = acc;
        else {
            int c = (i < N_AQI) ? i + 18 : i - N_AQI;
            s_T[e][c * 2 + (sel - 2)] = acc;
        }
    }
    __syncthreads();
    // s_full is DEAD from here; its bytes become the A tiles.

    // ---- Phase 3: masked UNNORMALIZED exp -> fp16x2 into A tile ----
    // Max-tree only; sum is computed by the tensor core in phase 4 (ones-MMA).
    // Lanes 27/28 zero this row's K-pad bytes [108,128).
    {
        const int e = wid >> 2, w4 = wid & 3;
        const bool act = (lane < 27);
        const int c0 = 2 * lane, c1 = c0 + 1;
        float4 tv = act ? *reinterpret_cast<const float4*>(&s_T[e][c0 * 2])
                        : make_float4(0.f, 0.f, 0.f, 0.f);
        const bool meo0 = (c0 < 18), meo1 = (c1 < 18);
        const uint32_t colOff = (uint32_t)(4 * lane);
        unsigned char* tileA = s_U[e].A;

        for (int i = w4; i < NTOT; i += 4) {
            const int rb = (i < N_AQI) ? 0 : 1;
            const uint32_t swrow = (uint32_t)((i & 7) << 4);
            if (lane == 27)
                *reinterpret_cast<uint32_t*>(tileA + i * 128 + (108u ^ swrow)) = 0u;
            if (lane == 28)
                *reinterpret_cast<float4*>(tileA + i * 128 + (112u ^ swrow)) =
                    make_float4(0.f, 0.f, 0.f, 0.f);

            float e0 = -3.4e38f, e1 = -3.4e38f;
            if (act) {
                unsigned long long M = g_maskP[i];
                float2 sv = *reinterpret_cast<const float2*>(&s_S[e][i * 2]);
                float2 bp = *reinterpret_cast<const float2*>(&g_biasP[i * 56 + c0]);
                float s0 = meo0 ? sv.y : sv.x;
                float s1 = meo1 ? sv.y : sv.x;
                float t0 = rb ? tv.y : tv.x;
                float t1 = rb ? tv.w : tv.z;
                float v0 = s0 + t0 + bp.x; v0 = (v0 >= 0.f) ? v0 : LALPHA * v0;
                float v1 = s1 + t1 + bp.y; v1 = (v1 >= 0.f) ? v1 : LALPHA * v1;
                e0 = ((M >> c0) & 1ull) ? v0 : NEGV;
                e1 = ((M >> c1) & 1ull) ? v1 : NEGV;
                if (c1 >= NTOT) e1 = -3.4e38f;
            }
            float mx = fmaxf(e0, e1);
            #pragma unroll
            for (int o = 16; o > 0; o >>= 1) mx = fmaxf(mx, __shfl_xor_sync(0xffffffffu, mx, o));
            if (act) {
                float p0 = __expf(e0 - mx);
                float p1 = __expf(e1 - mx);     // pad col / masked -> exp(-huge) = 0
                uint32_t off = (uint32_t)(i * 128) + (colOff ^ swrow);
                *reinterpret_cast<uint32_t*>(tileA + off) = pack2h(p0, p1);
            }
        }
    }
    __syncthreads();

    // ---- Phase 4: D = A @ B^T via mma.sync m16n8k16 fp16, plus ones-MMA row sums ----
    // warp: e = wid>>2; within batch: mg = (wid>>1)&1 (32 rows), ng = wid&1 (32 cols).
    {
        const int e = wid >> 2;
        const int mg = (wid >> 1) & 1, ng = wid & 1;
        const int lm = lane >> 3, lr = lane & 7;
        const uint32_t aBase = smem_u32(s_U[e].A);
        const uint32_t bBase = smem_u32(s_B[e]);
        const uint32_t swx = (uint32_t)(lr << 4);
        const uint32_t aCol = (uint32_t)((lm >> 1) << 4);
        const uint32_t bCol = (uint32_t)((lm & 1) << 4);
        const uint32_t ONES = 0x3C003C00u;     // fp16 (1.0, 1.0)
        const int bb = b0 + e;

        uint32_t aRB[2], bRB[2];
        #pragma unroll
        for (int mt = 0; mt < 2; mt++) {
            int row = mg * 32 + mt * 16 + (lm & 1) * 8 + lr;
            aRB[mt] = aBase + (uint32_t)(row * 128);
        }
        #pragma unroll
        for (int ntp = 0; ntp < 2; ntp++) {
            int row = ng * 32 + ntp * 16 + (lm >> 1) * 8 + lr;
            bRB[ntp] = bBase + (uint32_t)(row * 128);
        }

        float d[2][4][4];
        float dsum[2][4];
        #pragma unroll
        for (int mt = 0; mt < 2; mt++) {
            #pragma unroll
            for (int nt = 0; nt < 4; nt++)
                #pragma unroll
                for (int q = 0; q < 4; q++) d[mt][nt][q] = 0.f;
            #pragma unroll
            for (int q = 0; q < 4; q++) dsum[mt][q] = 0.f;
        }

        #pragma unroll
        for (int k = 0; k < 4; k++) {
            uint32_t a[2][4];
            #pragma unroll
            for (int mt = 0; mt < 2; mt++) {
                ldmx4(aRB[mt] + (((uint32_t)(k << 5) + aCol) ^ swx),
                      a[mt][0], a[mt][1], a[mt][2], a[mt][3]);
                mma16816(dsum[mt], a[mt], ONES, ONES);
            }
            #pragma unroll
            for (int ntp = 0; ntp < 2; ntp++) {
                uint32_t b0r, b1r, b2r, b3r;
                ldmx4(bRB[ntp] + (((uint32_t)(k << 5) + bCol) ^ swx), b0r, b1r, b2r, b3r);
                #pragma unroll
                for (int mt = 0; mt < 2; mt++) {
                    mma16816(d[mt][ntp * 2 + 0], a[mt], b0r, b1r);
                    mma16816(d[mt][ntp * 2 + 1], a[mt], b2r, b3r);
                }
            }
        }

        // Epilogue: normalize by ones-MMA row sums, direct float2 stores.
        const int r0l = lane >> 2;
        const int cl = (lane & 3) * 2;
        #pragma unroll
        for (int mt = 0; mt < 2; mt++) {
            const float inv0 = 1.f / dsum[mt][0];
            const float inv1 = 1.f / dsum[mt][2];
            #pragma unroll
            for (int nt = 0; nt < 4; nt++) {
                int r0 = mg * 32 + mt * 16 + r0l;
                int r1 = r0 + 8;
                int col = ng * 32 + nt * 8 + cl;
                if (r0 < NTOT) {
                    float* dst = (r0 < N_AQI)
                        ? out + ((size_t)bb * N_AQI + r0) * 64
                        : out + (size_t)BATCH * N_AQI * 64 + ((size_t)bb * N_MEO + (r0 - N_AQI)) * 64;
                    *reinterpret_cast<float2*>(dst + col) =
                        make_float2(d[mt][nt][0] * inv0, d[mt][nt][1] * inv0);
                }
                if (r1 < NTOT) {
                    float* dst = (r1 < N_AQI)
                        ? out + ((size_t)bb * N_AQI + r1) * 64
                        : out + (size_t)BATCH * N_AQI * 64 + ((size_t)bb * N_MEO + (r1 - N_AQI)) * 64;
                    *reinterpret_cast<float2*>(dst + col) =
                        make_float2(d[mt][nt][2] * inv1, d[mt][nt][3] * inv1);
                }
            }
        }
    }
}

extern "C" void kernel_launch(void* const* d_in, const int* in_sizes, int n_in,
                              void* d_out, int out_size)
{
    const float* aqi_inp      = (const float*)d_in[0];
    const float* meo_inp      = (const float*)d_in[1];
    const float* context_feat = (const float*)d_in[2];
    const float* adj_norm     = (const float*)d_in[3];
    const float* aqi_idE      = (const float*)d_in[4];
    const float* aqi_monthE   = (const float*)d_in[5];
    const float* aqi_weekdayE = (const float*)d_in[6];
    const float* aqi_hourE    = (const float*)d_in[7];
    const float* meo_windE    = (const float*)d_in[8];
    const float* meo_idE      = (const float*)d_in[9];
    const float* meo_monthE   = (const float*)d_in[10];
    const float* meo_weekdayE = (const float*)d_in[11];
    const float* meo_hourE    = (const float*)d_in[12];
    const float* W_xa         = (const float*)d_in[13];
    const float* W_xm         = (const float*)d_in[14];
    const float* W_ua         = (const float*)d_in[15];
    const float* W_um         = (const float*)d_in[16];
    const float* a_aa         = (const float*)d_in[17];
    const float* a_am         = (const float*)d_in[18];
    const float* a_ma         = (const float*)d_in[19];
    const float* a_mm         = (const float*)d_in[20];
    const int*   aqi_ex       = (const int*)d_in[21];
    const int*   meo_ex       = (const int*)d_in[22];
    const int*   adj          = (const int*)d_in[23];
    float* out = (float*)d_out;

    precompute_kernel<<<PRE_BLOCKS, 256>>>(context_feat, adj_norm,
                                           a_aa, a_am, a_ma, a_mm,
                                           W_ua, W_um, W_xa, W_xm, adj);
    hgat_kernel<<<BATCH / 2, 256>>>(aqi_inp, meo_inp,
                                    aqi_idE, aqi_monthE, aqi_weekdayE, aqi_hourE,
                                    meo_windE, meo_idE, meo_monthE, meo_weekdayE, meo_hourE,
                                    aqi_ex, meo_ex, out);
}

// round 13
// speedup vs baseline: 1.1489x; 1.0205x over previous
#include <cuda_runtime.h>
#include <cuda_fp16.h>
#include <cstddef>
#include <cstdint>

#define N_AQI 35
#define N_MEO 18
#define NTOT  53
#define F_OUT 64
#define CTXD  60
#define BATCH 4096
#define NEGV  (-1e12f)
#define LALPHA 0.2f

#define WT_STRIDE  20
#define FULL_STRIDE 28
#define PRE_BLOCKS 32

// K-column permutation: col c -> node j. MEO first (even-aligned pairs everywhere).
//   c in [0,18)  -> j = 35 + c   (MEO)
//   c in [18,53) -> j = c - 18   (AQI)

// ---------------- batch-independent precomputed state ----------------
__device__ __align__(16) float g_biasP[NTOT * 56];
__device__ __align__(16) unsigned long long g_maskP[NTOT];
__device__ __align__(16) float g_wsrc[2][2][FULL_STRIDE];
__device__ __align__(16) float g_wdst[2][2][FULL_STRIDE];
__device__ __align__(16) float g_WxaT[64 * WT_STRIDE];
__device__ __align__(16) float g_WxmT[64 * WT_STRIDE];

__global__ void precompute_kernel(
    const float* __restrict__ ctx,
    const float* __restrict__ adj_norm,
    const float* __restrict__ a_aa, const float* __restrict__ a_am,
    const float* __restrict__ a_ma, const float* __restrict__ a_mm,
    const float* __restrict__ W_ua, const float* __restrict__ W_um,
    const float* __restrict__ W_xa, const float* __restrict__ W_xm,
    const int*   __restrict__ adj)
{
    __shared__ float s_cs[NTOT][2];
    __shared__ float s_ct[NTOT][2];
    const int tid = threadIdx.x;
    const int gid = blockIdx.x * 256 + tid;
    const int gstr = PRE_BLOCKS * 256;
    const float* A[2][2] = {{a_aa, a_am}, {a_ma, a_mm}};

    for (int id = tid; id < NTOT * 4; id += 256) {
        int i = id % NTOT;
        int sel = id / NTOT;
        if (sel < 2) {
            int rb = (i < N_AQI) ? 0 : 1;
            const float* a = A[rb][sel];
            float acc = 0.f;
            for (int c = 0; c < CTXD; c++) acc += ctx[i * CTXD + c] * a[64 + c];
            s_cs[i][sel] = acc;
        } else {
            int rb = sel - 2;
            int cb = (i < N_AQI) ? 0 : 1;
            const float* a = A[rb][cb];
            float acc = 0.f;
            for (int c = 0; c < CTXD; c++) acc += ctx[i * CTXD + c] * a[188 + c];
            s_ct[i][rb] = acc;
        }
    }

    for (int id = gid; id < 2 * 2 * 2 * FULL_STRIDE; id += gstr) {
        int k = id % FULL_STRIDE;
        int r = id / FULL_STRIDE;
        int which = r >> 2;
        int t0 = (r >> 1) & 1;
        int t1 = r & 1;
        const float* W = (t0 == 0) ? W_ua : W_um;
        int K = (t0 == 0) ? 24 : 26;
        float acc = 0.f;
        if (k < K) {
            const float* a = (which == 0) ? A[t0][t1] : A[t1][t0];
            int off = (which == 0) ? 0 : 124;
            for (int f = 0; f < 64; f++) acc += W[k * 64 + f] * a[off + f];
        }
        if (which == 0) g_wsrc[t0][t1][k] = acc;
        else            g_wdst[t0][t1][k] = acc;
    }

    for (int id = gid; id < 64 * WT_STRIDE; id += gstr) {
        int f = id / WT_STRIDE, k = id % WT_STRIDE;
        g_WxaT[id] = (k < 16) ? W_xa[k * 64 + f] : 0.f;
        g_WxmT[id] = (k < 16) ? W_xm[k * 64 + f] : 0.f;
    }

    for (int i = gid; i < NTOT; i += gstr) {
        unsigned long long m = 0ull;
        for (int c = 0; c < NTOT; c++) {
            int j = (c < 18) ? 35 + c : c - 18;
            if (adj[i * NTOT + j] > 0) m |= (1ull << c);
        }
        g_maskP[i] = m;
    }
    __syncthreads();

    for (int id = gid; id < NTOT * 56; id += gstr) {
        int i = id / 56, c = id % 56;
        float v = 0.f;
        if (c < NTOT) {
            int j = (c < 18) ? 35 + c : c - 18;
            int rb = (i < N_AQI) ? 0 : 1;
            int cb = (j < N_AQI) ? 0 : 1;
            v = s_cs[i][cb] + s_ct[j][rb] + adj_norm[i * NTOT + j] * A[rb][cb][248];
        }
        g_biasP[id] = v;
    }
}

// ---------------- helpers ----------------
__device__ __forceinline__ unsigned long long fma2(unsigned long long a,
                                                   unsigned long long b,
                                                   unsigned long long c)
{
    unsigned long long d;
    asm("fma.rn.f32x2 %0, %1, %2, %3;" : "=l"(d) : "l"(a), "l"(b), "l"(c));
    return d;
}
__device__ __forceinline__ float lo32(unsigned long long v) { return __uint_as_float((unsigned)v); }
__device__ __forceinline__ float hi32(unsigned long long v) { return __uint_as_float((unsigned)(v >> 32)); }

__device__ __forceinline__ uint32_t smem_u32(const void* p) {
    uint32_t a;
    asm("{ .reg .u64 t; cvta.to.shared.u64 t, %1; cvt.u32.u64 %0, t; }" : "=r"(a) : "l"(p));
    return a;
}
__device__ __forceinline__ uint32_t pack2h(float a, float b) {
    __half2 v = __floats2half2_rn(a, b);    // a -> low halfword
    return *reinterpret_cast<uint32_t*>(&v);
}
__device__ __forceinline__ void ldmx4(uint32_t addr, uint32_t& r0, uint32_t& r1,
                                      uint32_t& r2, uint32_t& r3)
{
    asm volatile("ldmatrix.sync.aligned.m8n8.x4.shared.b16 {%0,%1,%2,%3}, [%4];"
                 : "=r"(r0), "=r"(r1), "=r"(r2), "=r"(r3) : "r"(addr));
}
__device__ __forceinline__ void mma16816(float* d, const uint32_t* a, uint32_t b0, uint32_t b1)
{
    asm volatile(
        "mma.sync.aligned.m16n8k16.row.col.f32.f16.f16.f32 "
        "{%0,%1,%2,%3}, {%4,%5,%6,%7}, {%8,%9}, {%0,%1,%2,%3};"
        : "+f"(d[0]), "+f"(d[1]), "+f"(d[2]), "+f"(d[3])
        : "r"(a[0]), "r"(a[1]), "r"(a[2]), "r"(a[3]), "r"(b0), "r"(b1));
}
// per-half barrier: half e uses named barrier 1+e with 128 threads
__device__ __forceinline__ void half_bar(int e) {
    asm volatile("bar.sync %0, 128;" :: "r"(1 + e) : "memory");
}

// A tile aliased with the gather buffer: s_full dead after phase 2; A written in phase 3.
union SmemAU {
    unsigned char A[64 * 128];
    float full[56 * FULL_STRIDE];
};

// ---------------- main kernel: TWO independent batch pipelines per CTA ----------------
__global__ __launch_bounds__(256, 4) void hgat_kernel(
    const float* __restrict__ aqi_inp, const float* __restrict__ meo_inp,
    const float* __restrict__ aqi_idE, const float* __restrict__ aqi_monthE,
    const float* __restrict__ aqi_weekdayE, const float* __restrict__ aqi_hourE,
    const float* __restrict__ meo_windE, const float* __restrict__ meo_idE,
    const float* __restrict__ meo_monthE, const float* __restrict__ meo_weekdayE,
    const float* __restrict__ meo_hourE,
    const int* __restrict__ aqi_ex, const int* __restrict__ meo_ex,
    float* __restrict__ out)
{
    __shared__ __align__(1024) SmemAU s_U[2];                 // A tiles / gather buffers
    __shared__ __align__(1024) unsigned char s_B[2][64 * 128];
    __shared__ __align__(16) float s_S[2][108];
    __shared__ __align__(16) float s_T[2][108];               // permuted-col; col 53 zeroed

    const int tid = threadIdx.x;
    const int wid = tid >> 5;
    const int lane = tid & 31;
    const int e = tid >> 7;              // half = batch index within CTA
    const int t128 = tid & 127;
    const int b0 = blockIdx.x * 2;
    const int bb = b0 + e;

    // ---- Phase 0 (per half): B K-pad zeroing, feature copy, embedding gather ----
    {
        const float4 z4 = make_float4(0.f, 0.f, 0.f, 0.f);
        if (t128 < 64) {
            int row = t128;
            unsigned char* base = s_B[e];
            uint32_t sw = (uint32_t)((row & 7) << 4);
            *reinterpret_cast<float4*>(base + row * 128 + (96u ^ sw)) = z4;
            *reinterpret_cast<float4*>(base + row * 128 + (112u ^ sw)) = z4;
        }
        // input features: 53 rows x 4 float4
        for (int id = t128; id < NTOT * 4; id += 128) {
            int row = id >> 2, q = id & 3;
            float4 v = (row < N_AQI)
                ? *reinterpret_cast<const float4*>(&aqi_inp[((size_t)bb * N_AQI + row) * 16 + 4 * q])
                : *reinterpret_cast<const float4*>(&meo_inp[((size_t)bb * N_MEO + (row - N_AQI)) * 16 + 4 * q]);
            *reinterpret_cast<float4*>(&s_U[e].full[row * FULL_STRIDE + 4 * q]) = v;
        }
        // AQI embeddings: 35 rows x 4 slots
        for (int id = t128; id < N_AQI * 4; id += 128) {
            int row = id >> 2, ee = id & 3;
            int ix = aqi_ex[((size_t)bb * N_AQI + row) * 4 + ee];
            const float* tab = (ee == 0) ? aqi_idE : (ee == 1) ? aqi_monthE
                             : (ee == 2) ? aqi_weekdayE : aqi_hourE;
            *reinterpret_cast<float2*>(&s_U[e].full[row * FULL_STRIDE + 16 + 2 * ee]) =
                *reinterpret_cast<const float2*>(&tab[ix * 2]);
        }
        // MEO embeddings: 18 rows x 5 slots
        for (int id = t128; id < N_MEO * 5; id += 128) {
            int row = id / 5, ee = id - row * 5;
            int ix = meo_ex[((size_t)bb * N_MEO + row) * 5 + ee];
            const float* tab = (ee == 0) ? meo_windE : (ee == 1) ? meo_idE
                             : (ee == 2) ? meo_monthE : (ee == 3) ? meo_weekdayE : meo_hourE;
            *reinterpret_cast<float2*>(&s_U[e].full[(N_AQI + row) * FULL_STRIDE + 16 + 2 * ee]) =
                *reinterpret_cast<const float2*>(&tab[ix * 2]);
        }
        // s_full pads: AQI cols 24-27, MEO cols 26-27; s_T col 53
        if (t128 < N_AQI) {
            *reinterpret_cast<float4*>(&s_U[e].full[t128 * FULL_STRIDE + 24]) = z4;
        } else if (t128 < NTOT) {
            s_U[e].full[t128 * FULL_STRIDE + 26] = 0.f;
            s_U[e].full[t128 * FULL_STRIDE + 27] = 0.f;
        } else if (t128 < NTOT + 2) {
            s_T[e][106 + (t128 - NTOT)] = 0.f;
        }
    }
    half_bar(e);

    // ---- Phase 1 (per half): projxT -> fp16 pairs into B tile ----
    // thread: f = (t128>>1)&63... keep original mapping: f = (tid>>1)&63, rg = tid&1
    {
        const int f = (t128 >> 1) & 63, rg = t128 & 1;
        const uint32_t sw = (uint32_t)((f & 7) << 4);
        unsigned char* rowB = s_B[e] + f * 128;
        const float* full = s_U[e].full;

        // MEO pass: pair p = rg + 2r, p < 9; c0 = 2p, nodes 35+c0, 36+c0
        {
            const float* wt = g_WxmT + f * WT_STRIDE;
            unsigned long long acc[5][2];
            #pragma unroll
            for (int r = 0; r < 5; r++) { acc[r][0] = 0ull; acc[r][1] = 0ull; }
            #pragma unroll
            for (int kg = 0; kg < 4; kg++) {
                ulonglong2 wv = *reinterpret_cast<const ulonglong2*>(wt + 4 * kg);
                #pragma unroll
                for (int r = 0; r < 5; r++) {
                    int p = rg + 2 * r;
                    if (p < 9) {
                        const float* x0 = &full[(N_AQI + 2 * p) * FULL_STRIDE + 4 * kg];
                        ulonglong2 a0 = *reinterpret_cast<const ulonglong2*>(x0);
                        ulonglong2 a1 = *reinterpret_cast<const ulonglong2*>(x0 + FULL_STRIDE);
                        acc[r][0] = fma2(wv.x, a0.x, acc[r][0]);
                        acc[r][0] = fma2(wv.y, a0.y, acc[r][0]);
                        acc[r][1] = fma2(wv.x, a1.x, acc[r][1]);
                        acc[r][1] = fma2(wv.y, a1.y, acc[r][1]);
                    }
                }
            }
            #pragma unroll
            for (int r = 0; r < 5; r++) {
                int p = rg + 2 * r;
                if (p < 9) {
                    float p0 = lo32(acc[r][0]) + hi32(acc[r][0]);
                    float p1 = lo32(acc[r][1]) + hi32(acc[r][1]);
                    uint32_t off = ((uint32_t)(4 * p)) ^ sw;
                    *reinterpret_cast<uint32_t*>(rowB + off) = pack2h(p0, p1);
                }
            }
        }
        // AQI pass: pair p = 9 + rg + 2r, p < 27; c0 = 2p, nodes c0-18, c0-17
        {
            const float* wt = g_WxaT + f * WT_STRIDE;
            unsigned long long acc[9][2];
            #pragma unroll
            for (int r = 0; r < 9; r++) { acc[r][0] = 0ull; acc[r][1] = 0ull; }
            #pragma unroll
            for (int kg = 0; kg < 4; kg++) {
                ulonglong2 wv = *reinterpret_cast<const ulonglong2*>(wt + 4 * kg);
                #pragma unroll
                for (int r = 0; r < 9; r++) {
                    int p = 9 + rg + 2 * r;
                    if (p < 27) {
                        const float* x0 = &full[(2 * p - 18) * FULL_STRIDE + 4 * kg];
                        ulonglong2 a0 = *reinterpret_cast<const ulonglong2*>(x0);
                        ulonglong2 a1 = *reinterpret_cast<const ulonglong2*>(x0 + FULL_STRIDE);
                        acc[r][0] = fma2(wv.x, a0.x, acc[r][0]);
                        acc[r][0] = fma2(wv.y, a0.y, acc[r][0]);
                        acc[r][1] = fma2(wv.x, a1.x, acc[r][1]);
                        acc[r][1] = fma2(wv.y, a1.y, acc[r][1]);
                    }
                }
            }
            #pragma unroll
            for (int r = 0; r < 9; r++) {
                int p = 9 + rg + 2 * r;
                if (p < 27) {
                    float p0 = lo32(acc[r][0]) + hi32(acc[r][0]);
                    float p1 = (p == 26) ? 0.f : lo32(acc[r][1]) + hi32(acc[r][1]);
                    uint32_t off = ((uint32_t)(4 * p)) ^ sw;
                    *reinterpret_cast<uint32_t*>(rowB + off) = pack2h(p0, p1);
                }
            }
        }
    }

    // ---- Phase 2 (per half): S[i][cb]; T -> permuted-col layout ----
    for (int id = t128; id < NTOT * 4; id += 128) {
        int i = id % NTOT;
        int sel = id / NTOT;
        int rt = (i < N_AQI) ? 0 : 1;
        const float4* xr = reinterpret_cast<const float4*>(&s_U[e].full[i * FULL_STRIDE]);
        const float4* wv = reinterpret_cast<const float4*>(
            (sel < 2) ? g_wsrc[rt][sel] : g_wdst[rt][sel - 2]);
        float acc = 0.f;
        #pragma unroll
        for (int m = 0; m < 7; m++) {
            float4 x = xr[m], w = wv[m];
            acc += x.x * w.x + x.y * w.y + x.z * w.z + x.w * w.w;
        }
        if (sel < 2) s_S[e][i * 2 + sel] = acc;
        else {
            int c = (i < N_AQI) ? i + 18 : i - N_AQI;
            s_T[e][c * 2 + (sel - 2)] = acc;
        }
    }
    half_bar(e);
    // s_full is DEAD from here; its bytes become the A tiles.

    // ---- Phase 3 (per half): masked UNNORMALIZED exp -> fp16x2 into A tile ----
    // Max-tree only; sum comes from ones-MMA in phase 4.
    {
        const int w4 = wid & 3;
        const bool act = (lane < 27);
        const int c0 = 2 * lane, c1 = c0 + 1;
        float4 tv = act ? *reinterpret_cast<const float4*>(&s_T[e][c0 * 2])
                        : make_float4(0.f, 0.f, 0.f, 0.f);
        const bool meo0 = (c0 < 18), meo1 = (c1 < 18);
        const uint32_t colOff = (uint32_t)(4 * lane);
        unsigned char* tileA = s_U[e].A;

        #pragma unroll 2
        for (int i = w4; i < NTOT; i += 4) {
            const int rb = (i < N_AQI) ? 0 : 1;
            const uint32_t swrow = (uint32_t)((i & 7) << 4);
            if (lane == 27)
                *reinterpret_cast<uint32_t*>(tileA + i * 128 + (108u ^ swrow)) = 0u;
            if (lane == 28)
                *reinterpret_cast<float4*>(tileA + i * 128 + (112u ^ swrow)) =
                    make_float4(0.f, 0.f, 0.f, 0.f);

            float e0 = -3.4e38f, e1 = -3.4e38f;
            if (act) {
                unsigned long long M = g_maskP[i];
                float2 sv = *reinterpret_cast<const float2*>(&s_S[e][i * 2]);
                float2 bp = *reinterpret_cast<const float2*>(&g_biasP[i * 56 + c0]);
                float s0 = meo0 ? sv.y : sv.x;
                float s1 = meo1 ? sv.y : sv.x;
                float t0 = rb ? tv.y : tv.x;
                float t1 = rb ? tv.w : tv.z;
                float v0 = s0 + t0 + bp.x; v0 = (v0 >= 0.f) ? v0 : LALPHA * v0;
                float v1 = s1 + t1 + bp.y; v1 = (v1 >= 0.f) ? v1 : LALPHA * v1;
                e0 = ((M >> c0) & 1ull) ? v0 : NEGV;
                e1 = ((M >> c1) & 1ull) ? v1 : NEGV;
                if (c1 >= NTOT) e1 = -3.4e38f;
            }
            float mx = fmaxf(e0, e1);
            #pragma unroll
            for (int o = 16; o > 0; o >>= 1) mx = fmaxf(mx, __shfl_xor_sync(0xffffffffu, mx, o));
            if (act) {
                float p0 = __expf(e0 - mx);
                float p1 = __expf(e1 - mx);     // pad col / masked -> exp(-huge) = 0
                uint32_t off = (uint32_t)(i * 128) + (colOff ^ swrow);
                *reinterpret_cast<uint32_t*>(tileA + off) = pack2h(p0, p1);
            }
        }
    }
    half_bar(e);

    // ---- Phase 4 (per half): D = A @ B^T via mma.sync fp16 + ones-MMA row sums ----
    // within half: mg = (wid>>1)&1 (32 rows), ng = wid&1 (32 cols).
    {
        const int mg = (wid >> 1) & 1, ng = wid & 1;
        const int lm = lane >> 3, lr = lane & 7;
        const uint32_t aBase = smem_u32(s_U[e].A);
        const uint32_t bBase = smem_u32(s_B[e]);
        const uint32_t swx = (uint32_t)(lr << 4);
        const uint32_t aCol = (uint32_t)((lm >> 1) << 4);
        const uint32_t bCol = (uint32_t)((lm & 1) << 4);
        const uint32_t ONES = 0x3C003C00u;     // fp16 (1.0, 1.0)

        uint32_t aRB[2], bRB[2];
        #pragma unroll
        for (int mt = 0; mt < 2; mt++) {
            int row = mg * 32 + mt * 16 + (lm & 1) * 8 + lr;
            aRB[mt] = aBase + (uint32_t)(row * 128);
        }
        #pragma unroll
        for (int ntp = 0; ntp < 2; ntp++) {
            int row = ng * 32 + ntp * 16 + (lm >> 1) * 8 + lr;
            bRB[ntp] = bBase + (uint32_t)(row * 128);
        }

        float d[2][4][4];
        float dsum[2][4];
        #pragma unroll
        for (int mt = 0; mt < 2; mt++) {
            #pragma unroll
            for (int nt = 0; nt < 4; nt++)
                #pragma unroll
                for (int q = 0; q < 4; q++) d[mt][nt][q] = 0.f;
            #pragma unroll
            for (int q = 0; q < 4; q++) dsum[mt][q] = 0.f;
        }

        #pragma unroll
        for (int k = 0; k < 4; k++) {
            uint32_t a[2][4];
            #pragma unroll
            for (int mt = 0; mt < 2; mt++) {
                ldmx4(aRB[mt] + (((uint32_t)(k << 5) + aCol) ^ swx),
                      a[mt][0], a[mt][1], a[mt][2], a[mt][3]);
                mma16816(dsum[mt], a[mt], ONES, ONES);
            }
            #pragma unroll
            for (int ntp = 0; ntp < 2; ntp++) {
                uint32_t b0r, b1r, b2r, b3r;
                ldmx4(bRB[ntp] + (((uint32_t)(k << 5) + bCol) ^ swx), b0r, b1r, b2r, b3r);
                #pragma unroll
                for (int mt = 0; mt < 2; mt++) {
                    mma16816(d[mt][ntp * 2 + 0], a[mt], b0r, b1r);
                    mma16816(d[mt][ntp * 2 + 1], a[mt], b2r, b3r);
                }
            }
        }

        // Epilogue: normalize by ones-MMA row sums, direct float2 stores.
        const int r0l = lane >> 2;
        const int cl = (lane & 3) * 2;
        #pragma unroll
        for (int mt = 0; mt < 2; mt++) {
            const float inv0 = 1.f / dsum[mt][0];
            const float inv1 = 1.f / dsum[mt][2];
            #pragma unroll
            for (int nt = 0; nt < 4; nt++) {
                int r0 = mg * 32 + mt * 16 + r0l;
                int r1 = r0 + 8;
                int col = ng * 32 + nt * 8 + cl;
                if (r0 < NTOT) {
                    float* dst = (r0 < N_AQI)
                        ? out + ((size_t)bb * N_AQI + r0) * 64
                        : out + (size_t)BATCH * N_AQI * 64 + ((size_t)bb * N_MEO + (r0 - N_AQI)) * 64;
                    *reinterpret_cast<float2*>(dst + col) =
                        make_float2(d[mt][nt][0] * inv0, d[mt][nt][1] * inv0);
                }
                if (r1 < NTOT) {
                    float* dst = (r1 < N_AQI)
                        ? out + ((size_t)bb * N_AQI + r1) * 64
                        : out + (size_t)BATCH * N_AQI * 64 + ((size_t)bb * N_MEO + (r1 - N_AQI)) * 64;
                    *reinterpret_cast<float2*>(dst + col) =
                        make_float2(d[mt][nt][2] * inv1, d[mt][nt][3] * inv1);
                }
            }
        }
    }
}

extern "C" void kernel_launch(void* const* d_in, const int* in_sizes, int n_in,
                              void* d_out, int out_size)
{
    const float* aqi_inp      = (const float*)d_in[0];
    const float* meo_inp      = (const float*)d_in[1];
    const float* context_feat = (const float*)d_in[2];
    const float* adj_norm     = (const float*)d_in[3];
    const float* aqi_idE      = (const float*)d_in[4];
    const float* aqi_monthE   = (const float*)d_in[5];
    const float* aqi_weekdayE = (const float*)d_in[6];
    const float* aqi_hourE    = (const float*)d_in[7];
    const float* meo_windE    = (const float*)d_in[8];
    const float* meo_idE      = (const float*)d_in[9];
    const float* meo_monthE   = (const float*)d_in[10];
    const float* meo_weekdayE = (const float*)d_in[11];
    const float* meo_hourE    = (const float*)d_in[12];
    const float* W_xa         = (const float*)d_in[13];
    const float* W_xm         = (const float*)d_in[14];
    const float* W_ua         = (const float*)d_in[15];
    const float* W_um         = (const float*)d_in[16];
    const float* a_aa         = (const float*)d_in[17];
    const float* a_am         = (const float*)d_in[18];
    const float* a_ma         = (const float*)d_in[19];
    const float* a_mm         = (const float*)d_in[20];
    const int*   aqi_ex       = (const int*)d_in[21];
    const int*   meo_ex       = (const int*)d_in[22];
    const int*   adj          = (const int*)d_in[23];
    float* out = (float*)d_out;

    precompute_kernel<<<PRE_BLOCKS, 256>>>(context_feat, adj_norm,
                                           a_aa, a_am, a_ma, a_mm,
                                           W_ua, W_um, W_xa, W_xm, adj);
    hgat_kernel<<<BATCH / 2, 256>>>(aqi_inp, meo_inp,
                                    aqi_idE, aqi_monthE, aqi_weekdayE, aqi_hourE,
                                    meo_windE, meo_idE, meo_monthE, meo_weekdayE, meo_hourE,
                                    aqi_ex, meo_ex, out);
}

// round 14
// speedup vs baseline: 1.3120x; 1.1419x over previous
#include <cuda_runtime.h>
#include <cuda_fp16.h>
#include <cstddef>
#include <cstdint>

#define N_AQI 35
#define N_MEO 18
#define NTOT  53
#define F_OUT 64
#define CTXD  60
#define BATCH 4096
#define NEGV  (-1e12f)
#define LALPHA 0.2f

#define FULL_STRIDE 28
#define PRE_BLOCKS 32

// K-column permutation: col c -> node j. MEO first.
//   c in [0,18)  -> j = 35 + c   (MEO)
//   c in [18,53) -> j = c - 18   (AQI)

// ---------------- batch-independent precomputed state ----------------
__device__ __align__(16) float g_biasP[NTOT * 56];
__device__ __align__(16) unsigned long long g_maskP[NTOT];
__device__ __align__(16) float g_wsrc[2][2][FULL_STRIDE];
__device__ __align__(16) float g_wdst[2][2][FULL_STRIDE];
// W2[f][k] fp16: k<16 -> W_xm[k][f], k>=16 -> W_xa[k-16][f]. 64x32, 64B rows.
__device__ __align__(16) __half g_W2[64 * 32];

__global__ void precompute_kernel(
    const float* __restrict__ ctx,
    const float* __restrict__ adj_norm,
    const float* __restrict__ a_aa, const float* __restrict__ a_am,
    const float* __restrict__ a_ma, const float* __restrict__ a_mm,
    const float* __restrict__ W_ua, const float* __restrict__ W_um,
    const float* __restrict__ W_xa, const float* __restrict__ W_xm,
    const int*   __restrict__ adj)
{
    __shared__ float s_cs[NTOT][2];
    __shared__ float s_ct[NTOT][2];
    const int tid = threadIdx.x;
    const int gid = blockIdx.x * 256 + tid;
    const int gstr = PRE_BLOCKS * 256;
    const float* A[2][2] = {{a_aa, a_am}, {a_ma, a_mm}};

    for (int id = tid; id < NTOT * 4; id += 256) {
        int i = id % NTOT;
        int sel = id / NTOT;
        if (sel < 2) {
            int rb = (i < N_AQI) ? 0 : 1;
            const float* a = A[rb][sel];
            float acc = 0.f;
            for (int c = 0; c < CTXD; c++) acc += ctx[i * CTXD + c] * a[64 + c];
            s_cs[i][sel] = acc;
        } else {
            int rb = sel - 2;
            int cb = (i < N_AQI) ? 0 : 1;
            const float* a = A[rb][cb];
            float acc = 0.f;
            for (int c = 0; c < CTXD; c++) acc += ctx[i * CTXD + c] * a[188 + c];
            s_ct[i][rb] = acc;
        }
    }

    for (int id = gid; id < 2 * 2 * 2 * FULL_STRIDE; id += gstr) {
        int k = id % FULL_STRIDE;
        int r = id / FULL_STRIDE;
        int which = r >> 2;
        int t0 = (r >> 1) & 1;
        int t1 = r & 1;
        const float* W = (t0 == 0) ? W_ua : W_um;
        int K = (t0 == 0) ? 24 : 26;
        float acc = 0.f;
        if (k < K) {
            const float* a = (which == 0) ? A[t0][t1] : A[t1][t0];
            int off = (which == 0) ? 0 : 124;
            for (int f = 0; f < 64; f++) acc += W[k * 64 + f] * a[off + f];
        }
        if (which == 0) g_wsrc[t0][t1][k] = acc;
        else            g_wdst[t0][t1][k] = acc;
    }

    // W2 fp16
    for (int id = gid; id < 64 * 32; id += gstr) {
        int f = id >> 5, k = id & 31;
        float v = (k < 16) ? W_xm[k * 64 + f] : W_xa[(k - 16) * 64 + f];
        g_W2[id] = __float2half(v);
    }

    for (int i = gid; i < NTOT; i += gstr) {
        unsigned long long m = 0ull;
        for (int c = 0; c < NTOT; c++) {
            int j = (c < 18) ? 35 + c : c - 18;
            if (adj[i * NTOT + j] > 0) m |= (1ull << c);
        }
        g_maskP[i] = m;
    }
    __syncthreads();

    for (int id = gid; id < NTOT * 56; id += gstr) {
        int i = id / 56, c = id % 56;
        float v = 0.f;
        if (c < NTOT) {
            int j = (c < 18) ? 35 + c : c - 18;
            int rb = (i < N_AQI) ? 0 : 1;
            int cb = (j < N_AQI) ? 0 : 1;
            v = s_cs[i][cb] + s_ct[j][rb] + adj_norm[i * NTOT + j] * A[rb][cb][248];
        }
        g_biasP[id] = v;
    }
}

// ---------------- helpers ----------------
__device__ __forceinline__ uint32_t smem_u32(const void* p) {
    uint32_t a;
    asm("{ .reg .u64 t; cvta.to.shared.u64 t, %1; cvt.u32.u64 %0, t; }" : "=r"(a) : "l"(p));
    return a;
}
__device__ __forceinline__ uint32_t pack2h(float a, float b) {
    __half2 v = __floats2half2_rn(a, b);    // a -> low halfword
    return *reinterpret_cast<uint32_t*>(&v);
}
__device__ __forceinline__ void ldmx4(uint32_t addr, uint32_t& r0, uint32_t& r1,
                                      uint32_t& r2, uint32_t& r3)
{
    asm volatile("ldmatrix.sync.aligned.m8n8.x4.shared.b16 {%0,%1,%2,%3}, [%4];"
                 : "=r"(r0), "=r"(r1), "=r"(r2), "=r"(r3) : "r"(addr));
}
__device__ __forceinline__ void mma16816(float* d, const uint32_t* a, uint32_t b0, uint32_t b1)
{
    asm volatile(
        "mma.sync.aligned.m16n8k16.row.col.f32.f16.f16.f32 "
        "{%0,%1,%2,%3}, {%4,%5,%6,%7}, {%8,%9}, {%0,%1,%2,%3};"
        : "+f"(d[0]), "+f"(d[1]), "+f"(d[2]), "+f"(d[3])
        : "r"(a[0]), "r"(a[1]), "r"(a[2]), "r"(a[3]), "r"(b0), "r"(b1));
}
__device__ __forceinline__ void half_bar(int e) {
    asm volatile("bar.sync %0, 128;" :: "r"(1 + e) : "memory");
}

// A/T tile aliased with the fp32 gather buffer (full dead after phase 2;
// attn written phase 3; T overwrites attn after MMA1 barrier).
union SmemAU {
    unsigned char A[64 * 128];
    float full[56 * FULL_STRIDE];
};

// ---------------- main kernel: TWO independent batch pipelines per CTA ----------------
__global__ __launch_bounds__(256, 4) void hgat_kernel(
    const float* __restrict__ aqi_inp, const float* __restrict__ meo_inp,
    const float* __restrict__ aqi_idE, const float* __restrict__ aqi_monthE,
    const float* __restrict__ aqi_weekdayE, const float* __restrict__ aqi_hourE,
    const float* __restrict__ meo_windE, const float* __restrict__ meo_idE,
    const float* __restrict__ meo_monthE, const float* __restrict__ meo_weekdayE,
    const float* __restrict__ meo_hourE,
    const int* __restrict__ aqi_ex, const int* __restrict__ meo_ex,
    float* __restrict__ out)
{
    __shared__ __align__(1024) SmemAU s_U[2];                 // attn/T tiles / gather buffers
    // s_B[e]: bytes [0,4096) = fullT (32 rows x 128B, swizzled);
    //         bytes [4096,8192) = W2 (64 rows x 64B, no swizzle)
    __shared__ __align__(1024) unsigned char s_B[2][64 * 128];
    __shared__ __align__(16) float s_S[2][108];
    __shared__ __align__(16) float s_T[2][108];               // permuted-col; col 53 zeroed

    const int tid = threadIdx.x;
    const int wid = tid >> 5;
    const int lane = tid & 31;
    const int e = tid >> 7;              // half = batch index within CTA
    const int t128 = tid & 127;
    const int w4 = wid & 3;
    const int b0 = blockIdx.x * 2;
    const int bb = b0 + e;

    // ---- Phase 0 (per half): zero fullT, stage W2, feature copy, embedding gather ----
    {
        const float4 z4 = make_float4(0.f, 0.f, 0.f, 0.f);
        // zero fullT region (4KB) and stage W2 (4KB)
        {
            float4* fz = reinterpret_cast<float4*>(s_B[e]);
            fz[t128] = z4;
            fz[t128 + 128] = z4;
            const float4* src = reinterpret_cast<const float4*>(g_W2);
            float4* dstW = reinterpret_cast<float4*>(s_B[e] + 4096);
            dstW[t128] = src[t128];
            dstW[t128 + 128] = src[t128 + 128];
        }
        // input features: 53 rows x 4 float4
        for (int id = t128; id < NTOT * 4; id += 128) {
            int row = id >> 2, q = id & 3;
            float4 v = (row < N_AQI)
                ? *reinterpret_cast<const float4*>(&aqi_inp[((size_t)bb * N_AQI + row) * 16 + 4 * q])
                : *reinterpret_cast<const float4*>(&meo_inp[((size_t)bb * N_MEO + (row - N_AQI)) * 16 + 4 * q]);
            *reinterpret_cast<float4*>(&s_U[e].full[row * FULL_STRIDE + 4 * q]) = v;
        }
        // AQI embeddings: 35 rows x 4 slots
        for (int id = t128; id < N_AQI * 4; id += 128) {
            int row = id >> 2, ee = id & 3;
            int ix = aqi_ex[((size_t)bb * N_AQI + row) * 4 + ee];
            const float* tab = (ee == 0) ? aqi_idE : (ee == 1) ? aqi_monthE
                             : (ee == 2) ? aqi_weekdayE : aqi_hourE;
            *reinterpret_cast<float2*>(&s_U[e].full[row * FULL_STRIDE + 16 + 2 * ee]) =
                *reinterpret_cast<const float2*>(&tab[ix * 2]);
        }
        // MEO embeddings: 18 rows x 5 slots
        for (int id = t128; id < N_MEO * 5; id += 128) {
            int row = id / 5, ee = id - row * 5;
            int ix = meo_ex[((size_t)bb * N_MEO + row) * 5 + ee];
            const float* tab = (ee == 0) ? meo_windE : (ee == 1) ? meo_idE
                             : (ee == 2) ? meo_monthE : (ee == 3) ? meo_weekdayE : meo_hourE;
            *reinterpret_cast<float2*>(&s_U[e].full[(N_AQI + row) * FULL_STRIDE + 16 + 2 * ee]) =
                *reinterpret_cast<const float2*>(&tab[ix * 2]);
        }
        // s_full pads: AQI cols 24-27, MEO cols 26-27; s_T col 53
        if (t128 < N_AQI) {
            *reinterpret_cast<float4*>(&s_U[e].full[t128 * FULL_STRIDE + 24]) = z4;
        } else if (t128 < NTOT) {
            s_U[e].full[t128 * FULL_STRIDE + 26] = 0.f;
            s_U[e].full[t128 * FULL_STRIDE + 27] = 0.f;
        } else if (t128 < NTOT + 2) {
            s_T[e][106 + (t128 - NTOT)] = 0.f;
        }
    }
    half_bar(e);

    // ---- Phase 2 (per half): S/T dots + fullT build (both read fp32 full) ----
    // fullT: row r<16 = MEO input feat r (cols 0-17), r>=16 = AQI feat r-16 (cols 18-52).
    for (int id = t128; id < 432; id += 128) {
        int r, p;
        if (id < 144) { r = id / 9; p = id % 9; }
        else { int id2 = id - 144; r = 16 + id2 / 18; p = 9 + id2 % 18; }
        float v0, v1;
        if (r < 16) {
            v0 = s_U[e].full[(N_AQI + 2 * p) * FULL_STRIDE + r];
            v1 = s_U[e].full[(N_AQI + 2 * p + 1) * FULL_STRIDE + r];
        } else {
            int rr = r - 16;
            v0 = s_U[e].full[(2 * p - 18) * FULL_STRIDE + rr];
            v1 = (p == 26) ? 0.f : s_U[e].full[(2 * p - 17) * FULL_STRIDE + rr];
        }
        uint32_t off = (uint32_t)(r * 128) + (((uint32_t)(4 * p)) ^ ((uint32_t)(r & 7) << 4));
        *reinterpret_cast<uint32_t*>(s_B[e] + off) = pack2h(v0, v1);
    }
    for (int id = t128; id < NTOT * 4; id += 128) {
        int i = id % NTOT;
        int sel = id / NTOT;
        int rt = (i < N_AQI) ? 0 : 1;
        const float4* xr = reinterpret_cast<const float4*>(&s_U[e].full[i * FULL_STRIDE]);
        const float4* wv = reinterpret_cast<const float4*>(
            (sel < 2) ? g_wsrc[rt][sel] : g_wdst[rt][sel - 2]);
        float acc = 0.f;
        #pragma unroll
        for (int m = 0; m < 7; m++) {
            float4 x = xr[m], w = wv[m];
            acc += x.x * w.x + x.y * w.y + x.z * w.z + x.w * w.w;
        }
        if (sel < 2) s_S[e][i * 2 + sel] = acc;
        else {
            int c = (i < N_AQI) ? i + 18 : i - N_AQI;
            s_T[e][c * 2 + (sel - 2)] = acc;
        }
    }
    half_bar(e);
    // fp32 full is DEAD from here; its bytes become the attn tile.

    // ---- Phase 3 (per half): masked UNNORMALIZED exp -> fp16x2 into attn tile ----
    {
        const bool act = (lane < 27);
        const int c0 = 2 * lane, c1 = c0 + 1;
        float4 tv = act ? *reinterpret_cast<const float4*>(&s_T[e][c0 * 2])
                        : make_float4(0.f, 0.f, 0.f, 0.f);
        const bool meo0 = (c0 < 18), meo1 = (c1 < 18);
        const uint32_t colOff = (uint32_t)(4 * lane);
        unsigned char* tileA = s_U[e].A;

        #pragma unroll 2
        for (int i = w4; i < NTOT; i += 4) {
            const int rb = (i < N_AQI) ? 0 : 1;
            const uint32_t swrow = (uint32_t)((i & 7) << 4);
            if (lane == 27)
                *reinterpret_cast<uint32_t*>(tileA + i * 128 + (108u ^ swrow)) = 0u;
            if (lane == 28)
                *reinterpret_cast<float4*>(tileA + i * 128 + (112u ^ swrow)) =
                    make_float4(0.f, 0.f, 0.f, 0.f);

            float e0 = -3.4e38f, e1 = -3.4e38f;
            if (act) {
                unsigned long long M = g_maskP[i];
                float2 sv = *reinterpret_cast<const float2*>(&s_S[e][i * 2]);
                float2 bp = *reinterpret_cast<const float2*>(&g_biasP[i * 56 + c0]);
                float s0 = meo0 ? sv.y : sv.x;
                float s1 = meo1 ? sv.y : sv.x;
                float t0 = rb ? tv.y : tv.x;
                float t1 = rb ? tv.w : tv.z;
                float v0 = s0 + t0 + bp.x; v0 = (v0 >= 0.f) ? v0 : LALPHA * v0;
                float v1 = s1 + t1 + bp.y; v1 = (v1 >= 0.f) ? v1 : LALPHA * v1;
                e0 = ((M >> c0) & 1ull) ? v0 : NEGV;
                e1 = ((M >> c1) & 1ull) ? v1 : NEGV;
                if (c1 >= NTOT) e1 = -3.4e38f;
            }
            float mx = fmaxf(e0, e1);
            #pragma unroll
            for (int o = 16; o > 0; o >>= 1) mx = fmaxf(mx, __shfl_xor_sync(0xffffffffu, mx, o));
            if (act) {
                float p0 = __expf(e0 - mx);
                float p1 = __expf(e1 - mx);
                uint32_t off = (uint32_t)(i * 128) + (colOff ^ swrow);
                *reinterpret_cast<uint32_t*>(tileA + off) = pack2h(p0, p1);
            }
        }
    }
    half_bar(e);

    // ---- Phase 4 (per half): MMA1 T = attn @ fullT^T (+sums), T->fp16, MMA2 D = T @ W2^T ----
    {
        const int mg = w4 & 1, ng = (w4 >> 1) & 1;
        const int lm = lane >> 3, lr = lane & 7;
        const uint32_t aBase = smem_u32(s_U[e].A);
        const uint32_t bBase = smem_u32(s_B[e]);
        const uint32_t w2Base = bBase + 4096u;
        const uint32_t swx = (uint32_t)(lr << 4);
        const uint32_t aCol = (uint32_t)((lm >> 1) << 4);
        const uint32_t bCol = (uint32_t)((lm & 1) << 4);
        const uint32_t ONES = 0x3C003C00u;

        // MMA1: per warp M=32 (mg), N=16 (ng); K=64
        uint32_t aRB[2];
        #pragma unroll
        for (int mt = 0; mt < 2; mt++) {
            int row = mg * 32 + mt * 16 + (lm & 1) * 8 + lr;
            aRB[mt] = aBase + (uint32_t)(row * 128);
        }
        const uint32_t bRB1 = bBase + (uint32_t)((ng * 16 + (lm >> 1) * 8 + lr) * 128);

        float d1[2][2][4];
        float dsum[2][4];
        #pragma unroll
        for (int mt = 0; mt < 2; mt++) {
            #pragma unroll
            for (int n8 = 0; n8 < 2; n8++)
                #pragma unroll
                for (int q = 0; q < 4; q++) d1[mt][n8][q] = 0.f;
            #pragma unroll
            for (int q = 0; q < 4; q++) dsum[mt][q] = 0.f;
        }

        #pragma unroll
        for (int k = 0; k < 4; k++) {
            uint32_t a[2][4];
            #pragma unroll
            for (int mt = 0; mt < 2; mt++) {
                ldmx4(aRB[mt] + (((uint32_t)(k << 5) + aCol) ^ swx),
                      a[mt][0], a[mt][1], a[mt][2], a[mt][3]);
                mma16816(dsum[mt], a[mt], ONES, ONES);
            }
            uint32_t b0r, b1r, b2r, b3r;
            ldmx4(bRB1 + (((uint32_t)(k << 5) + bCol) ^ swx), b0r, b1r, b2r, b3r);
            #pragma unroll
            for (int mt = 0; mt < 2; mt++) {
                mma16816(d1[mt][0], a[mt], b0r, b1r);
                mma16816(d1[mt][1], a[mt], b2r, b3r);
            }
        }
        half_bar(e);   // all warps done reading attn tile

        // store T (fp16) into the attn region: 64 rows x 128B stride, bytes 0-63 (cols 0-31)
        {
            const int r0l = lane >> 2, cl = (lane & 3) * 2;
            unsigned char* tileT = s_U[e].A;
            #pragma unroll
            for (int mt = 0; mt < 2; mt++) {
                #pragma unroll
                for (int n8 = 0; n8 < 2; n8++) {
                    int row0 = mg * 32 + mt * 16 + r0l;
                    int row1 = row0 + 8;
                    int cc = ng * 16 + n8 * 8 + cl;
                    uint32_t o0 = (uint32_t)(row0 * 128) +
                                  (((uint32_t)(2 * cc)) ^ ((uint32_t)(row0 & 7) << 4));
                    uint32_t o1 = (uint32_t)(row1 * 128) +
                                  (((uint32_t)(2 * cc)) ^ ((uint32_t)(row1 & 7) << 4));
                    *reinterpret_cast<uint32_t*>(tileT + o0) = pack2h(d1[mt][n8][0], d1[mt][n8][1]);
                    *reinterpret_cast<uint32_t*>(tileT + o1) = pack2h(d1[mt][n8][2], d1[mt][n8][3]);
                }
            }
        }
        half_bar(e);   // T tile complete

        // MMA2: per warp M=32 (mg), N=32 (ng); K=32
        float d2[2][4][4];
        #pragma unroll
        for (int mt = 0; mt < 2; mt++)
            #pragma unroll
            for (int nt = 0; nt < 4; nt++)
                #pragma unroll
                for (int q = 0; q < 4; q++) d2[mt][nt][q] = 0.f;

        #pragma unroll
        for (int k2 = 0; k2 < 2; k2++) {
            uint32_t a2[2][4];
            #pragma unroll
            for (int mt = 0; mt < 2; mt++)
                ldmx4(aRB[mt] + (((uint32_t)(k2 << 5) + aCol) ^ swx),
                      a2[mt][0], a2[mt][1], a2[mt][2], a2[mt][3]);
            #pragma unroll
            for (int ntp = 0; ntp < 2; ntp++) {
                int f0 = ng * 32 + ntp * 16 + (lm >> 1) * 8 + lr;
                uint32_t baddr = w2Base + (uint32_t)(f0 * 64) + (uint32_t)(k2 << 5) + bCol;
                uint32_t b0r, b1r, b2r, b3r;
                ldmx4(baddr, b0r, b1r, b2r, b3r);
                #pragma unroll
                for (int mt = 0; mt < 2; mt++) {
                    mma16816(d2[mt][ntp * 2 + 0], a2[mt], b0r, b1r);
                    mma16816(d2[mt][ntp * 2 + 1], a2[mt], b2r, b3r);
                }
            }
        }

        // Epilogue: normalize by dsum, direct float2 stores.
        const int r0l = lane >> 2;
        const int cl = (lane & 3) * 2;
        #pragma unroll
        for (int mt = 0; mt < 2; mt++) {
            const float inv0 = 1.f / dsum[mt][0];
            const float inv1 = 1.f / dsum[mt][2];
            #pragma unroll
            for (int nt = 0; nt < 4; nt++) {
                int r0 = mg * 32 + mt * 16 + r0l;
                int r1 = r0 + 8;
                int col = ng * 32 + nt * 8 + cl;
                if (r0 < NTOT) {
                    float* dst = (r0 < N_AQI)
                        ? out + ((size_t)bb * N_AQI + r0) * 64
                        : out + (size_t)BATCH * N_AQI * 64 + ((size_t)bb * N_MEO + (r0 - N_AQI)) * 64;
                    *reinterpret_cast<float2*>(dst + col) =
                        make_float2(d2[mt][nt][0] * inv0, d2[mt][nt][1] * inv0);
                }
                if (r1 < NTOT) {
                    float* dst = (r1 < N_AQI)
                        ? out + ((size_t)bb * N_AQI + r1) * 64
                        : out + (size_t)BATCH * N_AQI * 64 + ((size_t)bb * N_MEO + (r1 - N_AQI)) * 64;
                    *reinterpret_cast<float2*>(dst + col) =
                        make_float2(d2[mt][nt][2] * inv1, d2[mt][nt][3] * inv1);
                }
            }
        }
    }
}

extern "C" void kernel_launch(void* const* d_in, const int* in_sizes, int n_in,
                              void* d_out, int out_size)
{
    const float* aqi_inp      = (const float*)d_in[0];
    const float* meo_inp      = (const float*)d_in[1];
    const float* context_feat = (const float*)d_in[2];
    const float* adj_norm     = (const float*)d_in[3];
    const float* aqi_idE      = (const float*)d_in[4];
    const float* aqi_monthE   = (const float*)d_in[5];
    const float* aqi_weekdayE = (const float*)d_in[6];
    const float* aqi_hourE    = (const float*)d_in[7];
    const float* meo_windE    = (const float*)d_in[8];
    const float* meo_idE      = (const float*)d_in[9];
    const float* meo_monthE   = (const float*)d_in[10];
    const float* meo_weekdayE = (const float*)d_in[11];
    const float* meo_hourE    = (const float*)d_in[12];
    const float* W_xa         = (const float*)d_in[13];
    const float* W_xm         = (const float*)d_in[14];
    const float* W_ua         = (const float*)d_in[15];
    const float* W_um         = (const float*)d_in[16];
    const float* a_aa         = (const float*)d_in[17];
    const float* a_am         = (const float*)d_in[18];
    const float* a_ma         = (const float*)d_in[19];
    const float* a_mm         = (const float*)d_in[20];
    const int*   aqi_ex       = (const int*)d_in[21];
    const int*   meo_ex       = (const int*)d_in[22];
    const int*   adj          = (const int*)d_in[23];
    float* out = (float*)d_out;

    precompute_kernel<<<PRE_BLOCKS, 256>>>(context_feat, adj_norm,
                                           a_aa, a_am, a_ma, a_mm,
                                           W_ua, W_um, W_xa, W_xm, adj);
    hgat_kernel<<<BATCH / 2, 256>>>(aqi_inp, meo_inp,
                                    aqi_idE, aqi_monthE, aqi_weekdayE, aqi_hourE,
                                    meo_windE, meo_idE, meo_monthE, meo_weekdayE, meo_hourE,
                                    aqi_ex, meo_ex, out);
}

// round 16
// speedup vs baseline: 1.4255x; 1.0865x over previous
#include <cuda_runtime.h>
#include <cuda_fp16.h>
#include <cstddef>
#include <cstdint>

#define N_AQI 35
#define N_MEO 18
#define NTOT  53
#define F_OUT 64
#define CTXD  60
#define BATCH 4096
#define NEGV  (-1e12f)
#define LALPHA 0.2f

#define FULL_STRIDE 28
#define PRE_BLOCKS 32

// K-column permutation: col c -> node j. MEO first.
//   c in [0,18)  -> j = 35 + c   (MEO)
//   c in [18,53) -> j = c - 18   (AQI)

// ---------------- batch-independent precomputed state ----------------
__device__ __align__(16) float g_biasP[NTOT * 56];
__device__ __align__(16) unsigned long long g_maskP[NTOT];
__device__ __align__(16) float g_wsrc[2][2][FULL_STRIDE];
__device__ __align__(16) float g_wdst[2][2][FULL_STRIDE];
// W2[f][k] fp16: k<16 -> W_xm[k][f], k>=16 -> W_xa[k-16][f]. 64x32, 64B rows.
__device__ __align__(16) __half g_W2[64 * 32];

__global__ void precompute_kernel(
    const float* __restrict__ ctx,
    const float* __restrict__ adj_norm,
    const float* __restrict__ a_aa, const float* __restrict__ a_am,
    const float* __restrict__ a_ma, const float* __restrict__ a_mm,
    const float* __restrict__ W_ua, const float* __restrict__ W_um,
    const float* __restrict__ W_xa, const float* __restrict__ W_xm,
    const int*   __restrict__ adj)
{
    __shared__ float s_cs[NTOT][2];
    __shared__ float s_ct[NTOT][2];
    const int tid = threadIdx.x;
    const int gid = blockIdx.x * 256 + tid;
    const int gstr = PRE_BLOCKS * 256;
    const float* A[2][2] = {{a_aa, a_am}, {a_ma, a_mm}};

    for (int id = tid; id < NTOT * 4; id += 256) {
        int i = id % NTOT;
        int sel = id / NTOT;
        if (sel < 2) {
            int rb = (i < N_AQI) ? 0 : 1;
            const float* a = A[rb][sel];
            float acc = 0.f;
            for (int c = 0; c < CTXD; c++) acc += ctx[i * CTXD + c] * a[64 + c];
            s_cs[i][sel] = acc;
        } else {
            int rb = sel - 2;
            int cb = (i < N_AQI) ? 0 : 1;
            const float* a = A[rb][cb];
            float acc = 0.f;
            for (int c = 0; c < CTXD; c++) acc += ctx[i * CTXD + c] * a[188 + c];
            s_ct[i][rb] = acc;
        }
    }

    for (int id = gid; id < 2 * 2 * 2 * FULL_STRIDE; id += gstr) {
        int k = id % FULL_STRIDE;
        int r = id / FULL_STRIDE;
        int which = r >> 2;
        int t0 = (r >> 1) & 1;
        int t1 = r & 1;
        const float* W = (t0 == 0) ? W_ua : W_um;
        int K = (t0 == 0) ? 24 : 26;
        float acc = 0.f;
        if (k < K) {
            const float* a = (which == 0) ? A[t0][t1] : A[t1][t0];
            int off = (which == 0) ? 0 : 124;
            for (int f = 0; f < 64; f++) acc += W[k * 64 + f] * a[off + f];
        }
        if (which == 0) g_wsrc[t0][t1][k] = acc;
        else            g_wdst[t0][t1][k] = acc;
    }

    // W2 fp16
    for (int id = gid; id < 64 * 32; id += gstr) {
        int f = id >> 5, k = id & 31;
        float v = (k < 16) ? W_xm[k * 64 + f] : W_xa[(k - 16) * 64 + f];
        g_W2[id] = __float2half(v);
    }

    for (int i = gid; i < NTOT; i += gstr) {
        unsigned long long m = 0ull;
        for (int c = 0; c < NTOT; c++) {
            int j = (c < 18) ? 35 + c : c - 18;
            if (adj[i * NTOT + j] > 0) m |= (1ull << c);
        }
        g_maskP[i] = m;
    }
    __syncthreads();

    for (int id = gid; id < NTOT * 56; id += gstr) {
        int i = id / 56, c = id % 56;
        float v = 0.f;
        if (c < NTOT) {
            int j = (c < 18) ? 35 + c : c - 18;
            int rb = (i < N_AQI) ? 0 : 1;
            int cb = (j < N_AQI) ? 0 : 1;
            v = s_cs[i][cb] + s_ct[j][rb] + adj_norm[i * NTOT + j] * A[rb][cb][248];
        }
        g_biasP[id] = v;
    }
}

// ---------------- helpers ----------------
__device__ __forceinline__ uint32_t smem_u32(const void* p) {
    uint32_t a;
    asm("{ .reg .u64 t; cvta.to.shared.u64 t, %1; cvt.u32.u64 %0, t; }" : "=r"(a) : "l"(p));
    return a;
}
__device__ __forceinline__ uint32_t pack2h(float a, float b) {
    __half2 v = __floats2half2_rn(a, b);    // a -> low halfword
    return *reinterpret_cast<uint32_t*>(&v);
}
__device__ __forceinline__ void ldmx4(uint32_t addr, uint32_t& r0, uint32_t& r1,
                                      uint32_t& r2, uint32_t& r3)
{
    asm volatile("ldmatrix.sync.aligned.m8n8.x4.shared.b16 {%0,%1,%2,%3}, [%4];"
                 : "=r"(r0), "=r"(r1), "=r"(r2), "=r"(r3) : "r"(addr));
}
__device__ __forceinline__ void mma16816(float* d, const uint32_t* a, uint32_t b0, uint32_t b1)
{
    asm volatile(
        "mma.sync.aligned.m16n8k16.row.col.f32.f16.f16.f32 "
        "{%0,%1,%2,%3}, {%4,%5,%6,%7}, {%8,%9}, {%0,%1,%2,%3};"
        : "+f"(d[0]), "+f"(d[1]), "+f"(d[2]), "+f"(d[3])
        : "r"(a[0]), "r"(a[1]), "r"(a[2]), "r"(a[3]), "r"(b0), "r"(b1));
}
__device__ __forceinline__ void half_bar(int e) {
    asm volatile("bar.sync %0, 128;" :: "r"(1 + e) : "memory");
}

// A/T tile aliased with the fp32 gather buffer (full dead after phase 2;
// attn written phase 3; T overwrites attn after MMA1 barrier).
union SmemAU {
    unsigned char A[64 * 128];
    float full[56 * FULL_STRIDE];
};

// ---------------- main kernel: TWO independent batch pipelines per CTA ----------------
__global__ __launch_bounds__(256, 4) void hgat_kernel(
    const float* __restrict__ aqi_inp, const float* __restrict__ meo_inp,
    const float* __restrict__ aqi_idE, const float* __restrict__ aqi_monthE,
    const float* __restrict__ aqi_weekdayE, const float* __restrict__ aqi_hourE,
    const float* __restrict__ meo_windE, const float* __restrict__ meo_idE,
    const float* __restrict__ meo_monthE, const float* __restrict__ meo_weekdayE,
    const float* __restrict__ meo_hourE,
    const int* __restrict__ aqi_ex, const int* __restrict__ meo_ex,
    float* __restrict__ out)
{
    __shared__ __align__(1024) SmemAU s_U[2];                 // attn/T tiles / gather buffers
    // s_B[e]: bytes [0,4096) = fullT (32 rows x 128B, swizzled);
    //         bytes [4096,8192) = W2 (64 rows x 64B, no swizzle)
    __shared__ __align__(1024) unsigned char s_B[2][64 * 128];
    __shared__ __align__(16) float s_S[2][108];
    __shared__ __align__(16) float s_T[2][108];               // permuted-col; col 53 zeroed
    __shared__ __align__(16) float s_biasS[NTOT * 56];        // batch-invariant, CTA-shared
    __shared__ __align__(16) unsigned long long s_maskS[NTOT];

    const int tid = threadIdx.x;
    const int wid = tid >> 5;
    const int lane = tid & 31;
    const int e = tid >> 7;              // half = batch index within CTA
    const int t128 = tid & 127;
    const int w4 = wid & 3;
    const int b0 = blockIdx.x * 2;
    const int bb = b0 + e;

    // ---- Phase 0: stage bias/mask (CTA-wide), zero fullT, stage W2, gather (per half) ----
    {
        const float4 z4 = make_float4(0.f, 0.f, 0.f, 0.f);
        // CTA-wide: stage bias (742 float4) + masks
        {
            const float4* srcB = reinterpret_cast<const float4*>(g_biasP);
            float4* dstB = reinterpret_cast<float4*>(s_biasS);
            #pragma unroll
            for (int it = 0; it < 3; it++) {
                int i = tid + it * 256;
                if (i < (NTOT * 56) / 4) dstB[i] = srcB[i];
            }
            if (tid < NTOT) s_maskS[tid] = g_maskP[tid];
        }
        // per-half: zero fullT region (4KB) and stage W2 (4KB)
        {
            float4* fz = reinterpret_cast<float4*>(s_B[e]);
            fz[t128] = z4;
            fz[t128 + 128] = z4;
            const float4* src = reinterpret_cast<const float4*>(g_W2);
            float4* dstW = reinterpret_cast<float4*>(s_B[e] + 4096);
            dstW[t128] = src[t128];
            dstW[t128 + 128] = src[t128 + 128];
        }
        // input features: 53 rows x 4 float4
        for (int id = t128; id < NTOT * 4; id += 128) {
            int row = id >> 2, q = id & 3;
            float4 v = (row < N_AQI)
                ? *reinterpret_cast<const float4*>(&aqi_inp[((size_t)bb * N_AQI + row) * 16 + 4 * q])
                : *reinterpret_cast<const float4*>(&meo_inp[((size_t)bb * N_MEO + (row - N_AQI)) * 16 + 4 * q]);
            *reinterpret_cast<float4*>(&s_U[e].full[row * FULL_STRIDE + 4 * q]) = v;
        }
        // AQI embeddings: 35 rows x 4 slots
        for (int id = t128; id < N_AQI * 4; id += 128) {
            int row = id >> 2, ee = id & 3;
            int ix = aqi_ex[((size_t)bb * N_AQI + row) * 4 + ee];
            const float* tab = (ee == 0) ? aqi_idE : (ee == 1) ? aqi_monthE
                             : (ee == 2) ? aqi_weekdayE : aqi_hourE;
            *reinterpret_cast<float2*>(&s_U[e].full[row * FULL_STRIDE + 16 + 2 * ee]) =
                *reinterpret_cast<const float2*>(&tab[ix * 2]);
        }
        // MEO embeddings: 18 rows x 5 slots
        for (int id = t128; id < N_MEO * 5; id += 128) {
            int row = id / 5, ee = id - row * 5;
            int ix = meo_ex[((size_t)bb * N_MEO + row) * 5 + ee];
            const float* tab = (ee == 0) ? meo_windE : (ee == 1) ? meo_idE
                             : (ee == 2) ? meo_monthE : (ee == 3) ? meo_weekdayE : meo_hourE;
            *reinterpret_cast<float2*>(&s_U[e].full[(N_AQI + row) * FULL_STRIDE + 16 + 2 * ee]) =
                *reinterpret_cast<const float2*>(&tab[ix * 2]);
        }
        // s_full pads: AQI cols 24-27, MEO cols 26-27; s_T col 53
        if (t128 < N_AQI) {
            *reinterpret_cast<float4*>(&s_U[e].full[t128 * FULL_STRIDE + 24]) = z4;
        } else if (t128 < NTOT) {
            s_U[e].full[t128 * FULL_STRIDE + 26] = 0.f;
            s_U[e].full[t128 * FULL_STRIDE + 27] = 0.f;
        } else if (t128 < NTOT + 2) {
            s_T[e][106 + (t128 - NTOT)] = 0.f;
        }
    }
    __syncthreads();    // bias/mask staged for whole CTA; per-half data also ready

    // ---- Phase 2 (per half): S/T dots + fullT build (both read fp32 full) ----
    // fullT: row r<16 = MEO input feat r (cols 0-17), r>=16 = AQI feat r-16 (cols 18-52).
    for (int id = t128; id < 432; id += 128) {
        int r, p;
        if (id < 144) { r = id / 9; p = id % 9; }
        else { int id2 = id - 144; r = 16 + id2 / 18; p = 9 + id2 % 18; }
        float v0, v1;
        if (r < 16) {
            v0 = s_U[e].full[(N_AQI + 2 * p) * FULL_STRIDE + r];
            v1 = s_U[e].full[(N_AQI + 2 * p + 1) * FULL_STRIDE + r];
        } else {
            int rr = r - 16;
            v0 = s_U[e].full[(2 * p - 18) * FULL_STRIDE + rr];
            v1 = (p == 26) ? 0.f : s_U[e].full[(2 * p - 17) * FULL_STRIDE + rr];
        }
        uint32_t off = (uint32_t)(r * 128) + (((uint32_t)(4 * p)) ^ ((uint32_t)(r & 7) << 4));
        *reinterpret_cast<uint32_t*>(s_B[e] + off) = pack2h(v0, v1);
    }
    for (int id = t128; id < NTOT * 4; id += 128) {
        int i = id % NTOT;
        int sel = id / NTOT;
        int rt = (i < N_AQI) ? 0 : 1;
        const float4* xr = reinterpret_cast<const float4*>(&s_U[e].full[i * FULL_STRIDE]);
        const float4* wv = reinterpret_cast<const float4*>(
            (sel < 2) ? g_wsrc[rt][sel] : g_wdst[rt][sel - 2]);
        float acc = 0.f;
        #pragma unroll
        for (int m = 0; m < 7; m++) {
            float4 x = xr[m], w = wv[m];
            acc += x.x * w.x + x.y * w.y + x.z * w.z + x.w * w.w;
        }
        if (sel < 2) s_S[e][i * 2 + sel] = acc;
        else {
            int c = (i < N_AQI) ? i + 18 : i - N_AQI;
            s_T[e][c * 2 + (sel - 2)] = acc;
        }
    }
    half_bar(e);
    // fp32 full is DEAD from here; its bytes become the attn tile.

    // ---- Phase 3 (per half): masked UNNORMALIZED exp -> fp16x2 into attn tile ----
    {
        const bool act = (lane < 27);
        const int c0 = 2 * lane, c1 = c0 + 1;
        float4 tv = act ? *reinterpret_cast<const float4*>(&s_T[e][c0 * 2])
                        : make_float4(0.f, 0.f, 0.f, 0.f);
        const bool meo0 = (c0 < 18), meo1 = (c1 < 18);
        const uint32_t colOff = (uint32_t)(4 * lane);
        unsigned char* tileA = s_U[e].A;

        #pragma unroll 2
        for (int i = w4; i < NTOT; i += 4) {
            const int rb = (i < N_AQI) ? 0 : 1;
            const uint32_t swrow = (uint32_t)((i & 7) << 4);
            if (lane == 27)
                *reinterpret_cast<uint32_t*>(tileA + i * 128 + (108u ^ swrow)) = 0u;
            if (lane == 28)
                *reinterpret_cast<float4*>(tileA + i * 128 + (112u ^ swrow)) =
                    make_float4(0.f, 0.f, 0.f, 0.f);

            float e0 = -3.4e38f, e1 = -3.4e38f;
            if (act) {
                unsigned long long M = s_maskS[i];
                float2 sv = *reinterpret_cast<const float2*>(&s_S[e][i * 2]);
                float2 bp = *reinterpret_cast<const float2*>(&s_biasS[i * 56 + c0]);
                float s0 = meo0 ? sv.y : sv.x;
                float s1 = meo1 ? sv.y : sv.x;
                float t0 = rb ? tv.y : tv.x;
                float t1 = rb ? tv.w : tv.z;
                float v0 = s0 + t0 + bp.x; v0 = (v0 >= 0.f) ? v0 : LALPHA * v0;
                float v1 = s1 + t1 + bp.y; v1 = (v1 >= 0.f) ? v1 : LALPHA * v1;
                e0 = ((M >> c0) & 1ull) ? v0 : NEGV;
                e1 = ((M >> c1) & 1ull) ? v1 : NEGV;
                if (c1 >= NTOT) e1 = -3.4e38f;
            }
            float mx = fmaxf(e0, e1);
            #pragma unroll
            for (int o = 16; o > 0; o >>= 1) mx = fmaxf(mx, __shfl_xor_sync(0xffffffffu, mx, o));
            if (act) {
                float p0 = __expf(e0 - mx);
                float p1 = __expf(e1 - mx);
                uint32_t off = (uint32_t)(i * 128) + (colOff ^ swrow);
                *reinterpret_cast<uint32_t*>(tileA + off) = pack2h(p0, p1);
            }
        }
    }
    half_bar(e);

    // ---- Phase 4 (per half): MMA1 T = attn @ fullT^T (+sums), T->fp16, MMA2 D = T @ W2^T ----
    {
        const int mg = w4 & 1, ng = (w4 >> 1) & 1;
        const int lm = lane >> 3, lr = lane & 7;
        const uint32_t aBase = smem_u32(s_U[e].A);
        const uint32_t bBase = smem_u32(s_B[e]);
        const uint32_t w2Base = bBase + 4096u;
        const uint32_t swx = (uint32_t)(lr << 4);
        const uint32_t aCol = (uint32_t)((lm >> 1) << 4);
        const uint32_t bCol = (uint32_t)((lm & 1) << 4);
        const uint32_t ONES = 0x3C003C00u;

        // MMA1: per warp M=32 (mg), N=16 (ng); K=64
        uint32_t aRB[2];
        #pragma unroll
        for (int mt = 0; mt < 2; mt++) {
            int row = mg * 32 + mt * 16 + (lm & 1) * 8 + lr;
            aRB[mt] = aBase + (uint32_t)(row * 128);
        }
        const uint32_t bRB1 = bBase + (uint32_t)((ng * 16 + (lm >> 1) * 8 + lr) * 128);

        float d1[2][2][4];
        float dsum[2][4];
        #pragma unroll
        for (int mt = 0; mt < 2; mt++) {
            #pragma unroll
            for (int n8 = 0; n8 < 2; n8++)
                #pragma unroll
                for (int q = 0; q < 4; q++) d1[mt][n8][q] = 0.f;
            #pragma unroll
            for (int q = 0; q < 4; q++) dsum[mt][q] = 0.f;
        }

        #pragma unroll
        for (int k = 0; k < 4; k++) {
            uint32_t a[2][4];
            #pragma unroll
            for (int mt = 0; mt < 2; mt++) {
                ldmx4(aRB[mt] + (((uint32_t)(k << 5) + aCol) ^ swx),
                      a[mt][0], a[mt][1], a[mt][2], a[mt][3]);
                mma16816(dsum[mt], a[mt], ONES, ONES);
            }
            uint32_t b0r, b1r, b2r, b3r;
            ldmx4(bRB1 + (((uint32_t)(k << 5) + bCol) ^ swx), b0r, b1r, b2r, b3r);
            #pragma unroll
            for (int mt = 0; mt < 2; mt++) {
                mma16816(d1[mt][0], a[mt], b0r, b1r);
                mma16816(d1[mt][1], a[mt], b2r, b3r);
            }
        }
        half_bar(e);   // all warps done reading attn tile

        // store T (fp16) into the attn region: 64 rows x 128B stride, bytes 0-63 (cols 0-31)
        {
            const int r0l = lane >> 2, cl = (lane & 3) * 2;
            unsigned char* tileT = s_U[e].A;
            #pragma unroll
            for (int mt = 0; mt < 2; mt++) {
                #pragma unroll
                for (int n8 = 0; n8 < 2; n8++) {
                    int row0 = mg * 32 + mt * 16 + r0l;
                    int row1 = row0 + 8;
                    int cc = ng * 16 + n8 * 8 + cl;
                    uint32_t o0 = (uint32_t)(row0 * 128) +
                                  (((uint32_t)(2 * cc)) ^ ((uint32_t)(row0 & 7) << 4));
                    uint32_t o1 = (uint32_t)(row1 * 128) +
                                  (((uint32_t)(2 * cc)) ^ ((uint32_t)(row1 & 7) << 4));
                    *reinterpret_cast<uint32_t*>(tileT + o0) = pack2h(d1[mt][n8][0], d1[mt][n8][1]);
                    *reinterpret_cast<uint32_t*>(tileT + o1) = pack2h(d1[mt][n8][2], d1[mt][n8][3]);
                }
            }
        }
        half_bar(e);   // T tile complete

        // MMA2: per warp M=32 (mg), N=32 (ng); K=32
        float d2[2][4][4];
        #pragma unroll
        for (int mt = 0; mt < 2; mt++)
            #pragma unroll
            for (int nt = 0; nt < 4; nt++)
                #pragma unroll
                for (int q = 0; q < 4; q++) d2[mt][nt][q] = 0.f;

        #pragma unroll
        for (int k2 = 0; k2 < 2; k2++) {
            uint32_t a2[2][4];
            #pragma unroll
            for (int mt = 0; mt < 2; mt++)
                ldmx4(aRB[mt] + (((uint32_t)(k2 << 5) + aCol) ^ swx),
                      a2[mt][0], a2[mt][1], a2[mt][2], a2[mt][3]);
            #pragma unroll
            for (int ntp = 0; ntp < 2; ntp++) {
                int f0 = ng * 32 + ntp * 16 + (lm >> 1) * 8 + lr;
                uint32_t baddr = w2Base + (uint32_t)(f0 * 64) + (uint32_t)(k2 << 5) + bCol;
                uint32_t b0r, b1r, b2r, b3r;
                ldmx4(baddr, b0r, b1r, b2r, b3r);
                #pragma unroll
                for (int mt = 0; mt < 2; mt++) {
                    mma16816(d2[mt][ntp * 2 + 0], a2[mt], b0r, b1r);
                    mma16816(d2[mt][ntp * 2 + 1], a2[mt], b2r, b3r);
                }
            }
        }

        // Epilogue: normalize by dsum, direct float2 stores.
        const int r0l = lane >> 2;
        const int cl = (lane & 3) * 2;
        #pragma unroll
        for (int mt = 0; mt < 2; mt++) {
            const float inv0 = 1.f / dsum[mt][0];
            const float inv1 = 1.f / dsum[mt][2];
            #pragma unroll
            for (int nt = 0; nt < 4; nt++) {
                int r0 = mg * 32 + mt * 16 + r0l;
                int r1 = r0 + 8;
                int col = ng * 32 + nt * 8 + cl;
                if (r0 < NTOT) {
                    float* dst = (r0 < N_AQI)
                        ? out + ((size_t)bb * N_AQI + r0) * 64
                        : out + (size_t)BATCH * N_AQI * 64 + ((size_t)bb * N_MEO + (r0 - N_AQI)) * 64;
                    *reinterpret_cast<float2*>(dst + col) =
                        make_float2(d2[mt][nt][0] * inv0, d2[mt][nt][1] * inv0);
                }
                if (r1 < NTOT) {
                    float* dst = (r1 < N_AQI)
                        ? out + ((size_t)bb * N_AQI + r1) * 64
                        : out + (size_t)BATCH * N_AQI * 64 + ((size_t)bb * N_MEO + (r1 - N_AQI)) * 64;
                    *reinterpret_cast<float2*>(dst + col) =
                        make_float2(d2[mt][nt][2] * inv1, d2[mt][nt][3] * inv1);
                }
            }
        }
    }
}

extern "C" void kernel_launch(void* const* d_in, const int* in_sizes, int n_in,
                              void* d_out, int out_size)
{
    const float* aqi_inp      = (const float*)d_in[0];
    const float* meo_inp      = (const float*)d_in[1];
    const float* context_feat = (const float*)d_in[2];
    const float* adj_norm     = (const float*)d_in[3];
    const float* aqi_idE      = (const float*)d_in[4];
    const float* aqi_monthE   = (const float*)d_in[5];
    const float* aqi_weekdayE = (const float*)d_in[6];
    const float* aqi_hourE    = (const float*)d_in[7];
    const float* meo_windE    = (const float*)d_in[8];
    const float* meo_idE      = (const float*)d_in[9];
    const float* meo_monthE   = (const float*)d_in[10];
    const float* meo_weekdayE = (const float*)d_in[11];
    const float* meo_hourE    = (const float*)d_in[12];
    const float* W_xa         = (const float*)d_in[13];
    const float* W_xm         = (const float*)d_in[14];
    const float* W_ua         = (const float*)d_in[15];
    const float* W_um         = (const float*)d_in[16];
    const float* a_aa         = (const float*)d_in[17];
    const float* a_am         = (const float*)d_in[18];
    const float* a_ma         = (const float*)d_in[19];
    const float* a_mm         = (const float*)d_in[20];
    const int*   aqi_ex       = (const int*)d_in[21];
    const int*   meo_ex       = (const int*)d_in[22];
    const int*   adj          = (const int*)d_in[23];
    float* out = (float*)d_out;

    precompute_kernel<<<PRE_BLOCKS, 256>>>(context_feat, adj_norm,
                                           a_aa, a_am, a_ma, a_mm,
                                           W_ua, W_um, W_xa, W_xm, adj);
    hgat_kernel<<<BATCH / 2, 256>>>(aqi_inp, meo_inp,
                                    aqi_idE, aqi_monthE, aqi_weekdayE, aqi_hourE,
                                    meo_windE, meo_idE, meo_monthE, meo_weekdayE, meo_hourE,
                                    aqi_ex, meo_ex, out);
}

// round 17
// speedup vs baseline: 1.4870x; 1.0432x over previous
#include <cuda_runtime.h>
#include <cuda_fp16.h>
#include <cstddef>
#include <cstdint>

#define N_AQI 35
#define N_MEO 18
#define NTOT  53
#define F_OUT 64
#define CTXD  60
#define BATCH 4096
#define NEGV  (-1e12f)
#define LALPHA 0.2f

#define FULL_STRIDE 28
#define PRE_BLOCKS 32

// K-column permutation: col c -> node j. MEO first.
//   c in [0,18)  -> j = 35 + c   (MEO)
//   c in [18,53) -> j = c - 18   (AQI)

// ---------------- batch-independent precomputed state ----------------
__device__ __align__(16) float g_biasP[NTOT * 56];
__device__ __align__(16) unsigned long long g_maskP[NTOT];
__device__ __align__(16) float g_wsrc[2][2][FULL_STRIDE];
__device__ __align__(16) float g_wdst[2][2][FULL_STRIDE];
// W2[f][k] fp16: k<16 -> W_xm[k][f], k>=16 -> W_xa[k-16][f]. 64x32, 64B rows.
__device__ __align__(16) __half g_W2[64 * 32];

__global__ void precompute_kernel(
    const float* __restrict__ ctx,
    const float* __restrict__ adj_norm,
    const float* __restrict__ a_aa, const float* __restrict__ a_am,
    const float* __restrict__ a_ma, const float* __restrict__ a_mm,
    const float* __restrict__ W_ua, const float* __restrict__ W_um,
    const float* __restrict__ W_xa, const float* __restrict__ W_xm,
    const int*   __restrict__ adj)
{
    __shared__ float s_cs[NTOT][2];
    __shared__ float s_ct[NTOT][2];
    const int tid = threadIdx.x;
    const int gid = blockIdx.x * 256 + tid;
    const int gstr = PRE_BLOCKS * 256;
    const float* A[2][2] = {{a_aa, a_am}, {a_ma, a_mm}};

    for (int id = tid; id < NTOT * 4; id += 256) {
        int i = id % NTOT;
        int sel = id / NTOT;
        if (sel < 2) {
            int rb = (i < N_AQI) ? 0 : 1;
            const float* a = A[rb][sel];
            float acc = 0.f;
            for (int c = 0; c < CTXD; c++) acc += ctx[i * CTXD + c] * a[64 + c];
            s_cs[i][sel] = acc;
        } else {
            int rb = sel - 2;
            int cb = (i < N_AQI) ? 0 : 1;
            const float* a = A[rb][cb];
            float acc = 0.f;
            for (int c = 0; c < CTXD; c++) acc += ctx[i * CTXD + c] * a[188 + c];
            s_ct[i][rb] = acc;
        }
    }

    for (int id = gid; id < 2 * 2 * 2 * FULL_STRIDE; id += gstr) {
        int k = id % FULL_STRIDE;
        int r = id / FULL_STRIDE;
        int which = r >> 2;
        int t0 = (r >> 1) & 1;
        int t1 = r & 1;
        const float* W = (t0 == 0) ? W_ua : W_um;
        int K = (t0 == 0) ? 24 : 26;
        float acc = 0.f;
        if (k < K) {
            const float* a = (which == 0) ? A[t0][t1] : A[t1][t0];
            int off = (which == 0) ? 0 : 124;
            for (int f = 0; f < 64; f++) acc += W[k * 64 + f] * a[off + f];
        }
        if (which == 0) g_wsrc[t0][t1][k] = acc;
        else            g_wdst[t0][t1][k] = acc;
    }

    // W2 fp16
    for (int id = gid; id < 64 * 32; id += gstr) {
        int f = id >> 5, k = id & 31;
        float v = (k < 16) ? W_xm[k * 64 + f] : W_xa[(k - 16) * 64 + f];
        g_W2[id] = __float2half(v);
    }

    for (int i = gid; i < NTOT; i += gstr) {
        unsigned long long m = 0ull;
        for (int c = 0; c < NTOT; c++) {
            int j = (c < 18) ? 35 + c : c - 18;
            if (adj[i * NTOT + j] > 0) m |= (1ull << c);
        }
        g_maskP[i] = m;
    }
    __syncthreads();

    for (int id = gid; id < NTOT * 56; id += gstr) {
        int i = id / 56, c = id % 56;
        float v = 0.f;
        if (c < NTOT) {
            int j = (c < 18) ? 35 + c : c - 18;
            int rb = (i < N_AQI) ? 0 : 1;
            int cb = (j < N_AQI) ? 0 : 1;
            v = s_cs[i][cb] + s_ct[j][rb] + adj_norm[i * NTOT + j] * A[rb][cb][248];
        }
        g_biasP[id] = v;
    }
}

// ---------------- helpers ----------------
__device__ __forceinline__ uint32_t smem_u32(const void* p) {
    uint32_t a;
    asm("{ .reg .u64 t; cvta.to.shared.u64 t, %1; cvt.u32.u64 %0, t; }" : "=r"(a) : "l"(p));
    return a;
}
__device__ __forceinline__ uint32_t pack2h(float a, float b) {
    __half2 v = __floats2half2_rn(a, b);    // a -> low halfword
    return *reinterpret_cast<uint32_t*>(&v);
}
__device__ __forceinline__ void ldmx4(uint32_t addr, uint32_t& r0, uint32_t& r1,
                                      uint32_t& r2, uint32_t& r3)
{
    asm volatile("ldmatrix.sync.aligned.m8n8.x4.shared.b16 {%0,%1,%2,%3}, [%4];"
                 : "=r"(r0), "=r"(r1), "=r"(r2), "=r"(r3) : "r"(addr));
}
__device__ __forceinline__ void mma16816(float* d, const uint32_t* a, uint32_t b0, uint32_t b1)
{
    asm volatile(
        "mma.sync.aligned.m16n8k16.row.col.f32.f16.f16.f32 "
        "{%0,%1,%2,%3}, {%4,%5,%6,%7}, {%8,%9}, {%0,%1,%2,%3};"
        : "+f"(d[0]), "+f"(d[1]), "+f"(d[2]), "+f"(d[3])
        : "r"(a[0]), "r"(a[1]), "r"(a[2]), "r"(a[3]), "r"(b0), "r"(b1));
}
__device__ __forceinline__ void half_bar(int e) {
    asm volatile("bar.sync %0, 128;" :: "r"(1 + e) : "memory");
}
// single-instruction warp max for float (ordered-int transform, involution)
__device__ __forceinline__ float warp_max_f32(float v) {
    int xi = __float_as_int(v);
    xi ^= (xi >> 31) & 0x7fffffff;
    xi = __reduce_max_sync(0xffffffffu, xi);
    xi ^= (xi >> 31) & 0x7fffffff;
    return __int_as_float(xi);
}

// A/T tile aliased with the fp32 gather buffer (full dead after phase 2;
// attn written phase 3; T overwrites attn after MMA1 barrier).
union SmemAU {
    unsigned char A[64 * 128];
    float full[56 * FULL_STRIDE];
};

// ---------------- main kernel: TWO independent batch pipelines per CTA ----------------
__global__ __launch_bounds__(256, 4) void hgat_kernel(
    const float* __restrict__ aqi_inp, const float* __restrict__ meo_inp,
    const float* __restrict__ aqi_idE, const float* __restrict__ aqi_monthE,
    const float* __restrict__ aqi_weekdayE, const float* __restrict__ aqi_hourE,
    const float* __restrict__ meo_windE, const float* __restrict__ meo_idE,
    const float* __restrict__ meo_monthE, const float* __restrict__ meo_weekdayE,
    const float* __restrict__ meo_hourE,
    const int* __restrict__ aqi_ex, const int* __restrict__ meo_ex,
    float* __restrict__ out)
{
    __shared__ __align__(1024) SmemAU s_U[2];                 // attn/T tiles / gather buffers
    // s_B[e]: bytes [0,4096) = fullT (32 rows x 128B, swizzled);
    //         bytes [4096,8192) = W2 (64 rows x 64B, no swizzle)
    __shared__ __align__(1024) unsigned char s_B[2][64 * 128];
    __shared__ __align__(16) float s_S[2][108];
    __shared__ __align__(16) float s_T[2][108];               // permuted-col; col 53 zeroed
    __shared__ __align__(16) float s_biasS[NTOT * 56];        // batch-invariant, CTA-shared
    __shared__ __align__(16) unsigned long long s_maskS[NTOT];

    const int tid = threadIdx.x;
    const int wid = tid >> 5;
    const int lane = tid & 31;
    const int e = tid >> 7;              // half = batch index within CTA
    const int t128 = tid & 127;
    const int w4 = wid & 3;
    const int b0 = blockIdx.x * 2;
    const int bb = b0 + e;

    // ---- Phase 0: stage bias/mask (CTA-wide), zero fullT, stage W2, gather (per half) ----
    {
        const float4 z4 = make_float4(0.f, 0.f, 0.f, 0.f);
        // CTA-wide: stage bias (742 float4) + masks
        {
            const float4* srcB = reinterpret_cast<const float4*>(g_biasP);
            float4* dstB = reinterpret_cast<float4*>(s_biasS);
            #pragma unroll
            for (int it = 0; it < 3; it++) {
                int i = tid + it * 256;
                if (i < (NTOT * 56) / 4) dstB[i] = srcB[i];
            }
            if (tid < NTOT) s_maskS[tid] = g_maskP[tid];
        }
        // per-half: zero fullT region (4KB) and stage W2 (4KB)
        {
            float4* fz = reinterpret_cast<float4*>(s_B[e]);
            fz[t128] = z4;
            fz[t128 + 128] = z4;
            const float4* src = reinterpret_cast<const float4*>(g_W2);
            float4* dstW = reinterpret_cast<float4*>(s_B[e] + 4096);
            dstW[t128] = src[t128];
            dstW[t128 + 128] = src[t128 + 128];
        }
        // input features: 53 rows x 4 float4
        for (int id = t128; id < NTOT * 4; id += 128) {
            int row = id >> 2, q = id & 3;
            float4 v = (row < N_AQI)
                ? *reinterpret_cast<const float4*>(&aqi_inp[((size_t)bb * N_AQI + row) * 16 + 4 * q])
                : *reinterpret_cast<const float4*>(&meo_inp[((size_t)bb * N_MEO + (row - N_AQI)) * 16 + 4 * q]);
            *reinterpret_cast<float4*>(&s_U[e].full[row * FULL_STRIDE + 4 * q]) = v;
        }
        // AQI embeddings: 35 rows x 4 slots
        for (int id = t128; id < N_AQI * 4; id += 128) {
            int row = id >> 2, ee = id & 3;
            int ix = aqi_ex[((size_t)bb * N_AQI + row) * 4 + ee];
            const float* tab = (ee == 0) ? aqi_idE : (ee == 1) ? aqi_monthE
                             : (ee == 2) ? aqi_weekdayE : aqi_hourE;
            *reinterpret_cast<float2*>(&s_U[e].full[row * FULL_STRIDE + 16 + 2 * ee]) =
                *reinterpret_cast<const float2*>(&tab[ix * 2]);
        }
        // MEO embeddings: 18 rows x 5 slots
        for (int id = t128; id < N_MEO * 5; id += 128) {
            int row = id / 5, ee = id - row * 5;
            int ix = meo_ex[((size_t)bb * N_MEO + row) * 5 + ee];
            const float* tab = (ee == 0) ? meo_windE : (ee == 1) ? meo_idE
                             : (ee == 2) ? meo_monthE : (ee == 3) ? meo_weekdayE : meo_hourE;
            *reinterpret_cast<float2*>(&s_U[e].full[(N_AQI + row) * FULL_STRIDE + 16 + 2 * ee]) =
                *reinterpret_cast<const float2*>(&tab[ix * 2]);
        }
        // s_full pads: AQI cols 24-27, MEO cols 26-27; s_T col 53
        if (t128 < N_AQI) {
            *reinterpret_cast<float4*>(&s_U[e].full[t128 * FULL_STRIDE + 24]) = z4;
        } else if (t128 < NTOT) {
            s_U[e].full[t128 * FULL_STRIDE + 26] = 0.f;
            s_U[e].full[t128 * FULL_STRIDE + 27] = 0.f;
        } else if (t128 < NTOT + 2) {
            s_T[e][106 + (t128 - NTOT)] = 0.f;
        }
    }
    __syncthreads();    // bias/mask staged for whole CTA; per-half data also ready

    // ---- Phase 2 (per half): S/T dots + fullT build (both read fp32 full) ----
    // fullT: row r<16 = MEO input feat r (cols 0-17), r>=16 = AQI feat r-16 (cols 18-52).
    for (int id = t128; id < 432; id += 128) {
        int r, p;
        if (id < 144) { r = id / 9; p = id % 9; }
        else { int id2 = id - 144; r = 16 + id2 / 18; p = 9 + id2 % 18; }
        float v0, v1;
        if (r < 16) {
            v0 = s_U[e].full[(N_AQI + 2 * p) * FULL_STRIDE + r];
            v1 = s_U[e].full[(N_AQI + 2 * p + 1) * FULL_STRIDE + r];
        } else {
            int rr = r - 16;
            v0 = s_U[e].full[(2 * p - 18) * FULL_STRIDE + rr];
            v1 = (p == 26) ? 0.f : s_U[e].full[(2 * p - 17) * FULL_STRIDE + rr];
        }
        uint32_t off = (uint32_t)(r * 128) + (((uint32_t)(4 * p)) ^ ((uint32_t)(r & 7) << 4));
        *reinterpret_cast<uint32_t*>(s_B[e] + off) = pack2h(v0, v1);
    }
    // S/T dots: quads share row i -> LDS multicast (1 wf per LDS.128)
    for (int id = t128; id < NTOT * 4; id += 128) {
        int i = id >> 2;
        int sel = id & 3;
        int rt = (i < N_AQI) ? 0 : 1;
        const float4* xr = reinterpret_cast<const float4*>(&s_U[e].full[i * FULL_STRIDE]);
        const float4* wv = reinterpret_cast<const float4*>(
            (sel < 2) ? g_wsrc[rt][sel] : g_wdst[rt][sel - 2]);
        float acc = 0.f;
        #pragma unroll
        for (int m = 0; m < 7; m++) {
            float4 x = xr[m], w = wv[m];
            acc += x.x * w.x + x.y * w.y + x.z * w.z + x.w * w.w;
        }
        if (sel < 2) s_S[e][i * 2 + sel] = acc;
        else {
            int c = (i < N_AQI) ? i + 18 : i - N_AQI;
            s_T[e][c * 2 + (sel - 2)] = acc;
        }
    }
    half_bar(e);
    // fp32 full is DEAD from here; its bytes become the attn tile.

    // ---- Phase 3 (per half): masked UNNORMALIZED exp -> fp16x2 into attn tile ----
    // Single-instruction redux.sync warp max; sum via ones-MMA in phase 4.
    {
        const bool act = (lane < 27);
        const int c0 = 2 * lane, c1 = c0 + 1;
        float4 tv = act ? *reinterpret_cast<const float4*>(&s_T[e][c0 * 2])
                        : make_float4(0.f, 0.f, 0.f, 0.f);
        const bool meo0 = (c0 < 18), meo1 = (c1 < 18);
        const uint32_t colOff = (uint32_t)(4 * lane);
        unsigned char* tileA = s_U[e].A;

        #pragma unroll 2
        for (int i = w4; i < NTOT; i += 4) {
            const int rb = (i < N_AQI) ? 0 : 1;
            const uint32_t swrow = (uint32_t)((i & 7) << 4);
            if (lane == 27)
                *reinterpret_cast<uint32_t*>(tileA + i * 128 + (108u ^ swrow)) = 0u;
            if (lane == 28)
                *reinterpret_cast<float4*>(tileA + i * 128 + (112u ^ swrow)) =
                    make_float4(0.f, 0.f, 0.f, 0.f);

            float e0 = -3.4e38f, e1 = -3.4e38f;
            if (act) {
                unsigned long long M = s_maskS[i];
                float2 sv = *reinterpret_cast<const float2*>(&s_S[e][i * 2]);
                float2 bp = *reinterpret_cast<const float2*>(&s_biasS[i * 56 + c0]);
                float s0 = meo0 ? sv.y : sv.x;
                float s1 = meo1 ? sv.y : sv.x;
                float t0 = rb ? tv.y : tv.x;
                float t1 = rb ? tv.w : tv.z;
                float v0 = s0 + t0 + bp.x; v0 = (v0 >= 0.f) ? v0 : LALPHA * v0;
                float v1 = s1 + t1 + bp.y; v1 = (v1 >= 0.f) ? v1 : LALPHA * v1;
                e0 = ((M >> c0) & 1ull) ? v0 : NEGV;
                e1 = ((M >> c1) & 1ull) ? v1 : NEGV;
                if (c1 >= NTOT) e1 = -3.4e38f;
            }
            float mx = warp_max_f32(fmaxf(e0, e1));
            if (act) {
                float p0 = __expf(e0 - mx);
                float p1 = __expf(e1 - mx);
                uint32_t off = (uint32_t)(i * 128) + (colOff ^ swrow);
                *reinterpret_cast<uint32_t*>(tileA + off) = pack2h(p0, p1);
            }
        }
    }
    half_bar(e);

    // ---- Phase 4 (per half): MMA1 T = attn @ fullT^T (+sums), T->fp16, MMA2 D = T @ W2^T ----
    {
        const int mg = w4 & 1, ng = (w4 >> 1) & 1;
        const int lm = lane >> 3, lr = lane & 7;
        const uint32_t aBase = smem_u32(s_U[e].A);
        const uint32_t bBase = smem_u32(s_B[e]);
        const uint32_t w2Base = bBase + 4096u;
        const uint32_t swx = (uint32_t)(lr << 4);
        const uint32_t aCol = (uint32_t)((lm >> 1) << 4);
        const uint32_t bCol = (uint32_t)((lm & 1) << 4);
        const uint32_t ONES = 0x3C003C00u;

        // MMA1: per warp M=32 (mg), N=16 (ng); K=64
        uint32_t aRB[2];
        #pragma unroll
        for (int mt = 0; mt < 2; mt++) {
            int row = mg * 32 + mt * 16 + (lm & 1) * 8 + lr;
            aRB[mt] = aBase + (uint32_t)(row * 128);
        }
        const uint32_t bRB1 = bBase + (uint32_t)((ng * 16 + (lm >> 1) * 8 + lr) * 128);

        float d1[2][2][4];
        float dsum[2][4];
        #pragma unroll
        for (int mt = 0; mt < 2; mt++) {
            #pragma unroll
            for (int n8 = 0; n8 < 2; n8++)
                #pragma unroll
                for (int q = 0; q < 4; q++) d1[mt][n8][q] = 0.f;
            #pragma unroll
            for (int q = 0; q < 4; q++) dsum[mt][q] = 0.f;
        }

        #pragma unroll
        for (int k = 0; k < 4; k++) {
            uint32_t a[2][4];
            #pragma unroll
            for (int mt = 0; mt < 2; mt++) {
                ldmx4(aRB[mt] + (((uint32_t)(k << 5) + aCol) ^ swx),
                      a[mt][0], a[mt][1], a[mt][2], a[mt][3]);
                mma16816(dsum[mt], a[mt], ONES, ONES);
            }
            uint32_t b0r, b1r, b2r, b3r;
            ldmx4(bRB1 + (((uint32_t)(k << 5) + bCol) ^ swx), b0r, b1r, b2r, b3r);
            #pragma unroll
            for (int mt = 0; mt < 2; mt++) {
                mma16816(d1[mt][0], a[mt], b0r, b1r);
                mma16816(d1[mt][1], a[mt], b2r, b3r);
            }
        }
        half_bar(e);   // all warps done reading attn tile

        // store T (fp16) into the attn region: 64 rows x 128B stride, bytes 0-63 (cols 0-31)
        {
            const int r0l = lane >> 2, cl = (lane & 3) * 2;
            unsigned char* tileT = s_U[e].A;
            #pragma unroll
            for (int mt = 0; mt < 2; mt++) {
                #pragma unroll
                for (int n8 = 0; n8 < 2; n8++) {
                    int row0 = mg * 32 + mt * 16 + r0l;
                    int row1 = row0 + 8;
                    int cc = ng * 16 + n8 * 8 + cl;
                    uint32_t o0 = (uint32_t)(row0 * 128) +
                                  (((uint32_t)(2 * cc)) ^ ((uint32_t)(row0 & 7) << 4));
                    uint32_t o1 = (uint32_t)(row1 * 128) +
                                  (((uint32_t)(2 * cc)) ^ ((uint32_t)(row1 & 7) << 4));
                    *reinterpret_cast<uint32_t*>(tileT + o0) = pack2h(d1[mt][n8][0], d1[mt][n8][1]);
                    *reinterpret_cast<uint32_t*>(tileT + o1) = pack2h(d1[mt][n8][2], d1[mt][n8][3]);
                }
            }
        }
        half_bar(e);   // T tile complete

        // MMA2: per warp M=32 (mg), N=32 (ng); K=32
        float d2[2][4][4];
        #pragma unroll
        for (int mt = 0; mt < 2; mt++)
            #pragma unroll
            for (int nt = 0; nt < 4; nt++)
                #pragma unroll
                for (int q = 0; q < 4; q++) d2[mt][nt][q] = 0.f;

        #pragma unroll
        for (int k2 = 0; k2 < 2; k2++) {
            uint32_t a2[2][4];
            #pragma unroll
            for (int mt = 0; mt < 2; mt++)
                ldmx4(aRB[mt] + (((uint32_t)(k2 << 5) + aCol) ^ swx),
                      a2[mt][0], a2[mt][1], a2[mt][2], a2[mt][3]);
            #pragma unroll
            for (int ntp = 0; ntp < 2; ntp++) {
                int f0 = ng * 32 + ntp * 16 + (lm >> 1) * 8 + lr;
                uint32_t baddr = w2Base + (uint32_t)(f0 * 64) + (uint32_t)(k2 << 5) + bCol;
                uint32_t b0r, b1r, b2r, b3r;
                ldmx4(baddr, b0r, b1r, b2r, b3r);
                #pragma unroll
                for (int mt = 0; mt < 2; mt++) {
                    mma16816(d2[mt][ntp * 2 + 0], a2[mt], b0r, b1r);
                    mma16816(d2[mt][ntp * 2 + 1], a2[mt], b2r, b3r);
                }
            }
        }

        // Epilogue: normalize by dsum, direct float2 stores.
        const int r0l = lane >> 2;
        const int cl = (lane & 3) * 2;
        #pragma unroll
        for (int mt = 0; mt < 2; mt++) {
            const float inv0 = 1.f / dsum[mt][0];
            const float inv1 = 1.f / dsum[mt][2];
            #pragma unroll
            for (int nt = 0; nt < 4; nt++) {
                int r0 = mg * 32 + mt * 16 + r0l;
                int r1 = r0 + 8;
                int col = ng * 32 + nt * 8 + cl;
                if (r0 < NTOT) {
                    float* dst = (r0 < N_AQI)
                        ? out + ((size_t)bb * N_AQI + r0) * 64
                        : out + (size_t)BATCH * N_AQI * 64 + ((size_t)bb * N_MEO + (r0 - N_AQI)) * 64;
                    *reinterpret_cast<float2*>(dst + col) =
                        make_float2(d2[mt][nt][0] * inv0, d2[mt][nt][1] * inv0);
                }
                if (r1 < NTOT) {
                    float* dst = (r1 < N_AQI)
                        ? out + ((size_t)bb * N_AQI + r1) * 64
                        : out + (size_t)BATCH * N_AQI * 64 + ((size_t)bb * N_MEO + (r1 - N_AQI)) * 64;
                    *reinterpret_cast<float2*>(dst + col) =
                        make_float2(d2[mt][nt][2] * inv1, d2[mt][nt][3] * inv1);
                }
            }
        }
    }
}

extern "C" void kernel_launch(void* const* d_in, const int* in_sizes, int n_in,
                              void* d_out, int out_size)
{
    const float* aqi_inp      = (const float*)d_in[0];
    const float* meo_inp      = (const float*)d_in[1];
    const float* context_feat = (const float*)d_in[2];
    const float* adj_norm     = (const float*)d_in[3];
    const float* aqi_idE      = (const float*)d_in[4];
    const float* aqi_monthE   = (const float*)d_in[5];
    const float* aqi_weekdayE = (const float*)d_in[6];
    const float* aqi_hourE    = (const float*)d_in[7];
    const float* meo_windE    = (const float*)d_in[8];
    const float* meo_idE      = (const float*)d_in[9];
    const float* meo_monthE   = (const float*)d_in[10];
    const float* meo_weekdayE = (const float*)d_in[11];
    const float* meo_hourE    = (const float*)d_in[12];
    const float* W_xa         = (const float*)d_in[13];
    const float* W_xm         = (const float*)d_in[14];
    const float* W_ua         = (const float*)d_in[15];
    const float* W_um         = (const float*)d_in[16];
    const float* a_aa         = (const float*)d_in[17];
    const float* a_am         = (const float*)d_in[18];
    const float* a_ma         = (const float*)d_in[19];
    const float* a_mm         = (const float*)d_in[20];
    const int*   aqi_ex       = (const int*)d_in[21];
    const int*   meo_ex       = (const int*)d_in[22];
    const int*   adj          = (const int*)d_in[23];
    float* out = (float*)d_out;

    precompute_kernel<<<PRE_BLOCKS, 256>>>(context_feat, adj_norm,
                                           a_aa, a_am, a_ma, a_mm,
                                           W_ua, W_um, W_xa, W_xm, adj);
    hgat_kernel<<<BATCH / 2, 256>>>(aqi_inp, meo_inp,
                                    aqi_idE, aqi_monthE, aqi_weekdayE, aqi_hourE,
                                    meo_windE, meo_idE, meo_monthE, meo_weekdayE, meo_hourE,
                                    aqi_ex, meo_ex, out);
}